// round 1
// baseline (speedup 1.0000x reference)
#include <cuda_runtime.h>
#include <cstddef>

// Problem constants
#define BATCH 32
#define SEQ   1024
#define VDIM  128
#define EMB   768
#define H1    300
#define DDIM  200
#define MTOT  (BATCH*SEQ)   // 32768

// ---------------- scratch (static device arrays; no allocation) ----------------
__device__ __align__(128) float g_h[(size_t)MTOT * H1];     // 39.3 MB
__device__ __align__(128) float g_q[(size_t)MTOT * DDIM];   // 26.2 MB
__device__ __align__(128) float g_y[(size_t)MTOT * DDIM];   // 26.2 MB
__device__ __align__(128) float g_att[(size_t)MTOT * VDIM]; // 16.8 MB

// =====================================================================
// SGEMM: C[M,N] = act(A[M,K] @ B + bias)
//   TRANSB=false: B is [K,N] row-major
//   TRANSB=true : B is [N,K] row-major (C = A @ B^T)
// Tile: BM=128, BN=64, BK=16, 256 threads, 8x4 microtile.
// Requires: M % 128 == 0, K % 4 == 0, N % 4 == 0 (all true here).
// =====================================================================
template<bool TRANSB, bool RELU>
__global__ __launch_bounds__(256) void sgemm128x64(
    const float* __restrict__ A, const float* __restrict__ Bm,
    const float* __restrict__ bias, float* __restrict__ C,
    int M, int N, int K)
{
    __shared__ float As[16 * 132];  // [k][m], padded
    __shared__ float Bs[16 * 68];   // [k][n], padded

    const int tid = threadIdx.x;
    const int tx = tid & 15;
    const int ty = tid >> 4;
    const int m0 = blockIdx.y * 128;
    const int n0 = blockIdx.x * 64;

    float acc[8][4];
#pragma unroll
    for (int i = 0; i < 8; i++)
#pragma unroll
        for (int j = 0; j < 4; j++) acc[i][j] = 0.f;

    // loader lanes
    const int alm = tid >> 1;          // 0..127  (A row within tile)
    const int alk = (tid & 1) * 8;     // 0 or 8  (A k offset)
    const int bk  = tid >> 4;          // 0..15   (B k row, non-trans)
    const int bn4 = (tid & 15) * 4;    // 0..60   (B col offset, non-trans)
    const int btn = tid >> 2;          // 0..63   (B row n, trans)
    const int btk = (tid & 3) * 4;     // 0..12   (B k offset, trans)

    for (int k0 = 0; k0 < K; k0 += 16) {
        float4 a0 = make_float4(0.f,0.f,0.f,0.f);
        float4 a1 = a0, bv = a0;
        const float* Arow = A + (size_t)(m0 + alm) * K;
        if (k0 + alk < K)     a0 = *(const float4*)(Arow + k0 + alk);
        if (k0 + alk + 4 < K) a1 = *(const float4*)(Arow + k0 + alk + 4);
        if (TRANSB) {
            if (n0 + btn < N && k0 + btk < K)
                bv = *(const float4*)(Bm + (size_t)(n0 + btn) * K + k0 + btk);
        } else {
            if (k0 + bk < K && n0 + bn4 < N)
                bv = *(const float4*)(Bm + (size_t)(k0 + bk) * N + n0 + bn4);
        }
        __syncthreads();
        As[(alk + 0) * 132 + alm] = a0.x;
        As[(alk + 1) * 132 + alm] = a0.y;
        As[(alk + 2) * 132 + alm] = a0.z;
        As[(alk + 3) * 132 + alm] = a0.w;
        As[(alk + 4) * 132 + alm] = a1.x;
        As[(alk + 5) * 132 + alm] = a1.y;
        As[(alk + 6) * 132 + alm] = a1.z;
        As[(alk + 7) * 132 + alm] = a1.w;
        if (TRANSB) {
            Bs[(btk + 0) * 68 + btn] = bv.x;
            Bs[(btk + 1) * 68 + btn] = bv.y;
            Bs[(btk + 2) * 68 + btn] = bv.z;
            Bs[(btk + 3) * 68 + btn] = bv.w;
        } else {
            *(float4*)(Bs + bk * 68 + bn4) = bv;
        }
        __syncthreads();

#pragma unroll
        for (int k = 0; k < 16; k++) {
            float4 t0 = *(const float4*)(As + k * 132 + 8 * ty);
            float4 t1 = *(const float4*)(As + k * 132 + 8 * ty + 4);
            float4 tb = *(const float4*)(Bs + k * 68 + 4 * tx);
            float a[8] = {t0.x, t0.y, t0.z, t0.w, t1.x, t1.y, t1.z, t1.w};
            float b[4] = {tb.x, tb.y, tb.z, tb.w};
#pragma unroll
            for (int i = 0; i < 8; i++)
#pragma unroll
                for (int j = 0; j < 4; j++)
                    acc[i][j] += a[i] * b[j];
        }
    }

    const int nc = n0 + 4 * tx;
    float bb[4] = {0.f, 0.f, 0.f, 0.f};
    if (bias != nullptr && nc < N) {
        float4 t = *(const float4*)(bias + nc);
        bb[0] = t.x; bb[1] = t.y; bb[2] = t.z; bb[3] = t.w;
    }
    if (nc < N) {
#pragma unroll
        for (int i = 0; i < 8; i++) {
            int row = m0 + 8 * ty + i;
            float4 o;
            o.x = acc[i][0] + bb[0];
            o.y = acc[i][1] + bb[1];
            o.z = acc[i][2] + bb[2];
            o.w = acc[i][3] + bb[3];
            if (RELU) {
                o.x = fmaxf(o.x, 0.f); o.y = fmaxf(o.y, 0.f);
                o.z = fmaxf(o.z, 0.f); o.w = fmaxf(o.w, 0.f);
            }
            *(float4*)(C + (size_t)row * N + nc) = o;
        }
    }
}

// =====================================================================
// Fused attention:
//   scores[q,s] = dot(q[q,:], y[s,:])  (K=200), softmax over s (online),
//   out[q,v]   = sum_s P[q,s] * SRL[s,v]   (V=128)
// Block = 64 query rows of one batch; 256 threads (16x16).
// Thread (ty,tx): q rows = ty+16i (i<4); score cols s = tx+16j (j<4);
//                 out cols v = 4tx..4tx+3 and 64+4tx..64+4tx+3.
// =====================================================================
#define QS_STRIDE  204   // 200 + 4 pad
#define SRL_STRIDE 132   // 128 + 4 pad
#define PS_STRIDE  68    // 64 + 4 pad
#define ATTN_SMEM_FLOATS (64*QS_STRIDE*2 + 64*SRL_STRIDE + 64*PS_STRIDE)
#define ATTN_SMEM_BYTES  (ATTN_SMEM_FLOATS * 4)   // 155,648 B

__global__ __launch_bounds__(256) void attn_kernel(
    const float* __restrict__ q,    // [B,S,200]
    const float* __restrict__ y,    // [B,S,200]
    const float* __restrict__ srl,  // [B,S,128]
    float* __restrict__ out)        // [B,S,128]
{
    extern __shared__ float sm[];
    float* qs   = sm;                        // [64][204]
    float* ys   = qs   + 64 * QS_STRIDE;     // [64][204]
    float* srls = ys   + 64 * QS_STRIDE;     // [64][132]
    float* ps   = srls + 64 * SRL_STRIDE;    // [s][q] : [64][68]

    const int tid = threadIdx.x;
    const int tx = tid & 15;
    const int ty = tid >> 4;
    const int b  = blockIdx.y;
    const int q0 = blockIdx.x * 64;

    const float* qb = q   + ((size_t)b * SEQ + q0) * DDIM;
    const float* yb = y   + (size_t)b * SEQ * DDIM;
    const float* sb = srl + (size_t)b * SEQ * VDIM;

    // load q tile [64][200]
    for (int idx = tid; idx < 64 * 50; idx += 256) {
        int r = idx / 50, c = (idx % 50) * 4;
        *(float4*)(qs + r * QS_STRIDE + c) = *(const float4*)(qb + r * DDIM + c);
    }

    float m_i[4], l_i[4], acc[4][8];
#pragma unroll
    for (int i = 0; i < 4; i++) {
        m_i[i] = -1e30f; l_i[i] = 0.f;
#pragma unroll
        for (int g = 0; g < 8; g++) acc[i][g] = 0.f;
    }

    for (int s0 = 0; s0 < SEQ; s0 += 64) {
        __syncthreads();   // previous iter's PV reads finished
        for (int idx = tid; idx < 64 * 50; idx += 256) {
            int r = idx / 50, c = (idx % 50) * 4;
            *(float4*)(ys + r * QS_STRIDE + c) =
                *(const float4*)(yb + (size_t)(s0 + r) * DDIM + c);
        }
        for (int idx = tid; idx < 64 * 32; idx += 256) {
            int r = idx / 32, c = (idx % 32) * 4;
            *(float4*)(srls + r * SRL_STRIDE + c) =
                *(const float4*)(sb + (size_t)(s0 + r) * VDIM + c);
        }
        __syncthreads();

        // ---- scores tile: sc[i][j] = dot(q[ty+16i], y[tx+16j]) ----
        float sc[4][4];
#pragma unroll
        for (int i = 0; i < 4; i++)
#pragma unroll
            for (int j = 0; j < 4; j++) sc[i][j] = 0.f;

#pragma unroll 2
        for (int kk = 0; kk < DDIM; kk += 4) {
            float4 aq[4], ay[4];
#pragma unroll
            for (int i = 0; i < 4; i++)
                aq[i] = *(const float4*)(qs + (ty + 16 * i) * QS_STRIDE + kk);
#pragma unroll
            for (int j = 0; j < 4; j++)
                ay[j] = *(const float4*)(ys + (tx + 16 * j) * QS_STRIDE + kk);
#pragma unroll
            for (int i = 0; i < 4; i++)
#pragma unroll
                for (int j = 0; j < 4; j++) {
                    sc[i][j] += aq[i].x * ay[j].x;
                    sc[i][j] += aq[i].y * ay[j].y;
                    sc[i][j] += aq[i].z * ay[j].z;
                    sc[i][j] += aq[i].w * ay[j].w;
                }
        }

        // ---- online softmax update (reduce across 16 tx lanes) ----
        float p[4][4];
#pragma unroll
        for (int i = 0; i < 4; i++) {
            float tm = fmaxf(fmaxf(sc[i][0], sc[i][1]), fmaxf(sc[i][2], sc[i][3]));
            tm = fmaxf(tm, __shfl_xor_sync(0xffffffffu, tm, 1));
            tm = fmaxf(tm, __shfl_xor_sync(0xffffffffu, tm, 2));
            tm = fmaxf(tm, __shfl_xor_sync(0xffffffffu, tm, 4));
            tm = fmaxf(tm, __shfl_xor_sync(0xffffffffu, tm, 8));
            float mn = fmaxf(m_i[i], tm);
            float ts = 0.f;
#pragma unroll
            for (int j = 0; j < 4; j++) { p[i][j] = __expf(sc[i][j] - mn); ts += p[i][j]; }
            ts += __shfl_xor_sync(0xffffffffu, ts, 1);
            ts += __shfl_xor_sync(0xffffffffu, ts, 2);
            ts += __shfl_xor_sync(0xffffffffu, ts, 4);
            ts += __shfl_xor_sync(0xffffffffu, ts, 8);
            float f = __expf(m_i[i] - mn);
            l_i[i] = l_i[i] * f + ts;
            m_i[i] = mn;
#pragma unroll
            for (int g = 0; g < 8; g++) acc[i][g] *= f;
        }

        // ---- write P to smem transposed: ps[s][q] ----
#pragma unroll
        for (int i = 0; i < 4; i++)
#pragma unroll
            for (int j = 0; j < 4; j++)
                ps[(tx + 16 * j) * PS_STRIDE + (ty + 16 * i)] = p[i][j];
        __syncthreads();

        // ---- PV: acc[q][v] += P[q][s] * srl[s][v] ----
#pragma unroll 4
        for (int s = 0; s < 64; s++) {
            float rp[4];
#pragma unroll
            for (int i = 0; i < 4; i++) rp[i] = ps[s * PS_STRIDE + ty + 16 * i];
            float4 r0 = *(const float4*)(srls + s * SRL_STRIDE + 4 * tx);
            float4 r1 = *(const float4*)(srls + s * SRL_STRIDE + 64 + 4 * tx);
#pragma unroll
            for (int i = 0; i < 4; i++) {
                acc[i][0] += rp[i] * r0.x;
                acc[i][1] += rp[i] * r0.y;
                acc[i][2] += rp[i] * r0.z;
                acc[i][3] += rp[i] * r0.w;
                acc[i][4] += rp[i] * r1.x;
                acc[i][5] += rp[i] * r1.y;
                acc[i][6] += rp[i] * r1.z;
                acc[i][7] += rp[i] * r1.w;
            }
        }
    }

    // ---- normalize + store ----
#pragma unroll
    for (int i = 0; i < 4; i++) {
        float inv = 1.f / l_i[i];
        int row = q0 + ty + 16 * i;
        float* op = out + ((size_t)b * SEQ + row) * VDIM;
        float4 o0, o1;
        o0.x = acc[i][0] * inv; o0.y = acc[i][1] * inv;
        o0.z = acc[i][2] * inv; o0.w = acc[i][3] * inv;
        o1.x = acc[i][4] * inv; o1.y = acc[i][5] * inv;
        o1.z = acc[i][6] * inv; o1.w = acc[i][7] * inv;
        *(float4*)(op + 4 * tx) = o0;
        *(float4*)(op + 64 + 4 * tx) = o1;
    }
}

// =====================================================================
// launcher
// =====================================================================
extern "C" void kernel_launch(void* const* d_in, const int* in_sizes, int n_in,
                              void* d_out, int out_size)
{
    (void)in_sizes; (void)n_in; (void)out_size;
    const float* mem = (const float*)d_in[0];   // [32,1024,200]
    const float* srl = (const float*)d_in[1];   // [32,1024,128]
    const float* emb = (const float*)d_in[2];   // [32,1024,768]
    // d_in[3] word_id_emb: unused by reference
    const float* W1  = (const float*)d_in[4];   // [768,300]
    const float* b1  = (const float*)d_in[5];
    const float* W2  = (const float*)d_in[6];   // [300,200]
    const float* b2  = (const float*)d_in[7];
    const float* mat = (const float*)d_in[8];   // [200,200]
    const float* Wp  = (const float*)d_in[9];   // [128,128]
    const float* bp  = (const float*)d_in[10];
    float* outp = (float*)d_out;                // [32768,128]

    float *h, *qv, *yv, *att;
    cudaGetSymbolAddress((void**)&h,   g_h);
    cudaGetSymbolAddress((void**)&qv,  g_q);
    cudaGetSymbolAddress((void**)&yv,  g_y);
    cudaGetSymbolAddress((void**)&att, g_att);

    cudaFuncSetAttribute(attn_kernel,
                         cudaFuncAttributeMaxDynamicSharedMemorySize,
                         ATTN_SMEM_BYTES);

    // G1: h = relu(emb @ W1 + b1)   [32768,300]
    sgemm128x64<false, true><<<dim3(5, 256), 256>>>(emb, W1, b1, h, MTOT, H1, EMB);
    // G2: q = relu(h @ W2 + b2)     [32768,200]
    sgemm128x64<false, true><<<dim3(4, 256), 256>>>(h, W2, b2, qv, MTOT, DDIM, H1);
    // G3: y = mem @ matrix          [32768,200]
    sgemm128x64<false, false><<<dim3(4, 256), 256>>>(mem, mat, nullptr, yv, MTOT, DDIM, DDIM);
    // fused attention -> att        [32768,128]
    attn_kernel<<<dim3(SEQ / 64, BATCH), 256, ATTN_SMEM_BYTES>>>(qv, yv, srl, att);
    // G5: out = att @ Wp^T + bp     [32768,128]
    sgemm128x64<true, false><<<dim3(2, 256), 256>>>(att, Wp, bp, outp, MTOT, VDIM, VDIM);
}

// round 2
// speedup vs baseline: 1.0727x; 1.0727x over previous
#include <cuda_runtime.h>
#include <cstddef>

// Problem constants
#define BATCH 32
#define SEQ   1024
#define VDIM  128
#define EMB   768
#define H1    300
#define DDIM  200
#define MTOT  (BATCH*SEQ)   // 32768

// ---------------- scratch (static device arrays; no allocation) ----------------
__device__ __align__(128) float g_h[(size_t)MTOT * H1];     // 39.3 MB
__device__ __align__(128) float g_q[(size_t)MTOT * DDIM];   // 26.2 MB
__device__ __align__(128) float g_y[(size_t)MTOT * DDIM];   // 26.2 MB
__device__ __align__(128) float g_att[(size_t)MTOT * VDIM]; // 16.8 MB

// =====================================================================
// SGEMM: C[M,N] = act(A[M,K] @ B + bias)
//   TRANSB=false: B is [K,N] row-major
//   TRANSB=true : B is [N,K] row-major (C = A @ B^T)
// Tile: BM=128, BN=64, BK=16, 256 threads, 8x4 microtile.
// =====================================================================
template<bool TRANSB, bool RELU>
__global__ __launch_bounds__(256) void sgemm128x64(
    const float* __restrict__ A, const float* __restrict__ Bm,
    const float* __restrict__ bias, float* __restrict__ C,
    int M, int N, int K)
{
    __shared__ float As[16 * 132];  // [k][m], padded
    __shared__ float Bs[16 * 68];   // [k][n], padded

    const int tid = threadIdx.x;
    const int tx = tid & 15;
    const int ty = tid >> 4;
    const int m0 = blockIdx.y * 128;
    const int n0 = blockIdx.x * 64;

    float acc[8][4];
#pragma unroll
    for (int i = 0; i < 8; i++)
#pragma unroll
        for (int j = 0; j < 4; j++) acc[i][j] = 0.f;

    const int alm = tid >> 1;
    const int alk = (tid & 1) * 8;
    const int bk  = tid >> 4;
    const int bn4 = (tid & 15) * 4;
    const int btn = tid >> 2;
    const int btk = (tid & 3) * 4;

    for (int k0 = 0; k0 < K; k0 += 16) {
        float4 a0 = make_float4(0.f,0.f,0.f,0.f);
        float4 a1 = a0, bv = a0;
        const float* Arow = A + (size_t)(m0 + alm) * K;
        if (k0 + alk < K)     a0 = *(const float4*)(Arow + k0 + alk);
        if (k0 + alk + 4 < K) a1 = *(const float4*)(Arow + k0 + alk + 4);
        if (TRANSB) {
            if (n0 + btn < N && k0 + btk < K)
                bv = *(const float4*)(Bm + (size_t)(n0 + btn) * K + k0 + btk);
        } else {
            if (k0 + bk < K && n0 + bn4 < N)
                bv = *(const float4*)(Bm + (size_t)(k0 + bk) * N + n0 + bn4);
        }
        __syncthreads();
        As[(alk + 0) * 132 + alm] = a0.x;
        As[(alk + 1) * 132 + alm] = a0.y;
        As[(alk + 2) * 132 + alm] = a0.z;
        As[(alk + 3) * 132 + alm] = a0.w;
        As[(alk + 4) * 132 + alm] = a1.x;
        As[(alk + 5) * 132 + alm] = a1.y;
        As[(alk + 6) * 132 + alm] = a1.z;
        As[(alk + 7) * 132 + alm] = a1.w;
        if (TRANSB) {
            Bs[(btk + 0) * 68 + btn] = bv.x;
            Bs[(btk + 1) * 68 + btn] = bv.y;
            Bs[(btk + 2) * 68 + btn] = bv.z;
            Bs[(btk + 3) * 68 + btn] = bv.w;
        } else {
            *(float4*)(Bs + bk * 68 + bn4) = bv;
        }
        __syncthreads();

#pragma unroll
        for (int k = 0; k < 16; k++) {
            float4 t0 = *(const float4*)(As + k * 132 + 8 * ty);
            float4 t1 = *(const float4*)(As + k * 132 + 8 * ty + 4);
            float4 tb = *(const float4*)(Bs + k * 68 + 4 * tx);
            float a[8] = {t0.x, t0.y, t0.z, t0.w, t1.x, t1.y, t1.z, t1.w};
            float b[4] = {tb.x, tb.y, tb.z, tb.w};
#pragma unroll
            for (int i = 0; i < 8; i++)
#pragma unroll
                for (int j = 0; j < 4; j++)
                    acc[i][j] += a[i] * b[j];
        }
    }

    const int nc = n0 + 4 * tx;
    float bb[4] = {0.f, 0.f, 0.f, 0.f};
    if (bias != nullptr && nc < N) {
        float4 t = *(const float4*)(bias + nc);
        bb[0] = t.x; bb[1] = t.y; bb[2] = t.z; bb[3] = t.w;
    }
    if (nc < N) {
#pragma unroll
        for (int i = 0; i < 8; i++) {
            int row = m0 + 8 * ty + i;
            float4 o;
            o.x = acc[i][0] + bb[0];
            o.y = acc[i][1] + bb[1];
            o.z = acc[i][2] + bb[2];
            o.w = acc[i][3] + bb[3];
            if (RELU) {
                o.x = fmaxf(o.x, 0.f); o.y = fmaxf(o.y, 0.f);
                o.z = fmaxf(o.z, 0.f); o.w = fmaxf(o.w, 0.f);
            }
            *(float4*)(C + (size_t)row * N + nc) = o;
        }
    }
}

// =====================================================================
// Fused attention, v2: 128 queries x 64 keys per CTA, 512 threads.
// Thread grid 16(tx) x 32(ty). Per thread:
//   q rows  = 4*ty + i   (i<4, CONTIGUOUS -> float4 P reads in PV)
//   s cols  = tx + 16*j  (j<4)
//   out cols v = 4tx..4tx+3 and 64+4tx..64+4tx+3
// smem: qs[128][204] + ys[64][204] + srls[64][132] + ps[64][132] = 224.25 KB
// =====================================================================
#define QTILE 128
#define STILE 64
#define QS_STRIDE  204   // 200 + 4 pad
#define YS_STRIDE  204
#define SRL_STRIDE 132   // 128 + 4 pad
#define PS_STRIDE  132   // 128 q + 4 pad
#define ATTN_SMEM_FLOATS (QTILE*QS_STRIDE + STILE*YS_STRIDE + STILE*SRL_STRIDE + STILE*PS_STRIDE)
#define ATTN_SMEM_BYTES  (ATTN_SMEM_FLOATS * 4)   // 224,256 B

__global__ __launch_bounds__(512) void attn_kernel(
    const float* __restrict__ q,    // [B,S,200]
    const float* __restrict__ y,    // [B,S,200]
    const float* __restrict__ srl,  // [B,S,128]
    float* __restrict__ out)        // [B,S,128]
{
    extern __shared__ float sm[];
    float* qs   = sm;                        // [128][204]
    float* ys   = qs   + QTILE * QS_STRIDE;  // [64][204]
    float* srls = ys   + STILE * YS_STRIDE;  // [64][132]
    float* ps   = srls + STILE * SRL_STRIDE; // ps[s][q] : [64][132]

    const int tid = threadIdx.x;
    const int tx = tid & 15;
    const int ty = tid >> 4;         // 0..31
    const int b  = blockIdx.y;
    const int q0 = blockIdx.x * QTILE;

    const float* qb = q   + ((size_t)b * SEQ + q0) * DDIM;
    const float* yb = y   + (size_t)b * SEQ * DDIM;
    const float* sb = srl + (size_t)b * SEQ * VDIM;

    // load q tile [128][200]
    for (int idx = tid; idx < QTILE * 50; idx += 512) {
        int r = idx / 50, c = (idx % 50) * 4;
        *(float4*)(qs + r * QS_STRIDE + c) = *(const float4*)(qb + (size_t)r * DDIM + c);
    }

    float m_i[4], l_i[4], acc[4][8];
#pragma unroll
    for (int i = 0; i < 4; i++) {
        m_i[i] = -1e30f; l_i[i] = 0.f;
#pragma unroll
        for (int g = 0; g < 8; g++) acc[i][g] = 0.f;
    }

    for (int s0 = 0; s0 < SEQ; s0 += STILE) {
        __syncthreads();   // previous iter's PV reads finished (also covers q load)
        for (int idx = tid; idx < STILE * 50; idx += 512) {
            int r = idx / 50, c = (idx % 50) * 4;
            *(float4*)(ys + r * YS_STRIDE + c) =
                *(const float4*)(yb + (size_t)(s0 + r) * DDIM + c);
        }
        for (int idx = tid; idx < STILE * 32; idx += 512) {
            int r = idx >> 5, c = (idx & 31) * 4;
            *(float4*)(srls + r * SRL_STRIDE + c) =
                *(const float4*)(sb + (size_t)(s0 + r) * VDIM + c);
        }
        __syncthreads();

        // ---- scores tile: sc[i][j] = dot(q[4ty+i], y[tx+16j]) ----
        float sc[4][4];
#pragma unroll
        for (int i = 0; i < 4; i++)
#pragma unroll
            for (int j = 0; j < 4; j++) sc[i][j] = 0.f;

#pragma unroll 2
        for (int kk = 0; kk < DDIM; kk += 4) {
            float4 aq[4], ay[4];
#pragma unroll
            for (int i = 0; i < 4; i++)
                aq[i] = *(const float4*)(qs + (4 * ty + i) * QS_STRIDE + kk);
#pragma unroll
            for (int j = 0; j < 4; j++)
                ay[j] = *(const float4*)(ys + (tx + 16 * j) * YS_STRIDE + kk);
#pragma unroll
            for (int i = 0; i < 4; i++)
#pragma unroll
                for (int j = 0; j < 4; j++) {
                    sc[i][j] += aq[i].x * ay[j].x;
                    sc[i][j] += aq[i].y * ay[j].y;
                    sc[i][j] += aq[i].z * ay[j].z;
                    sc[i][j] += aq[i].w * ay[j].w;
                }
        }

        // ---- online softmax update (reduce across 16 tx lanes in-warp) ----
        float p[4][4];
#pragma unroll
        for (int i = 0; i < 4; i++) {
            float tm = fmaxf(fmaxf(sc[i][0], sc[i][1]), fmaxf(sc[i][2], sc[i][3]));
            tm = fmaxf(tm, __shfl_xor_sync(0xffffffffu, tm, 1));
            tm = fmaxf(tm, __shfl_xor_sync(0xffffffffu, tm, 2));
            tm = fmaxf(tm, __shfl_xor_sync(0xffffffffu, tm, 4));
            tm = fmaxf(tm, __shfl_xor_sync(0xffffffffu, tm, 8));
            float mn = fmaxf(m_i[i], tm);
            float ts = 0.f;
#pragma unroll
            for (int j = 0; j < 4; j++) { p[i][j] = __expf(sc[i][j] - mn); ts += p[i][j]; }
            ts += __shfl_xor_sync(0xffffffffu, ts, 1);
            ts += __shfl_xor_sync(0xffffffffu, ts, 2);
            ts += __shfl_xor_sync(0xffffffffu, ts, 4);
            ts += __shfl_xor_sync(0xffffffffu, ts, 8);
            float f = __expf(m_i[i] - mn);
            l_i[i] = l_i[i] * f + ts;
            m_i[i] = mn;
#pragma unroll
            for (int g = 0; g < 8; g++) acc[i][g] *= f;
        }

        // ---- write P to smem transposed: ps[s][q], q contiguous ----
#pragma unroll
        for (int j = 0; j < 4; j++)
#pragma unroll
            for (int i = 0; i < 4; i++)
                ps[(tx + 16 * j) * PS_STRIDE + (4 * ty + i)] = p[i][j];
        __syncthreads();

        // ---- PV: acc[q][v] += P[q][s] * srl[s][v] ----
#pragma unroll 4
        for (int s = 0; s < STILE; s++) {
            float4 rp = *(const float4*)(ps + s * PS_STRIDE + 4 * ty);
            float4 r0 = *(const float4*)(srls + s * SRL_STRIDE + 4 * tx);
            float4 r1 = *(const float4*)(srls + s * SRL_STRIDE + 64 + 4 * tx);
            float pv[4] = {rp.x, rp.y, rp.z, rp.w};
#pragma unroll
            for (int i = 0; i < 4; i++) {
                acc[i][0] += pv[i] * r0.x;
                acc[i][1] += pv[i] * r0.y;
                acc[i][2] += pv[i] * r0.z;
                acc[i][3] += pv[i] * r0.w;
                acc[i][4] += pv[i] * r1.x;
                acc[i][5] += pv[i] * r1.y;
                acc[i][6] += pv[i] * r1.z;
                acc[i][7] += pv[i] * r1.w;
            }
        }
    }

    // ---- normalize + store ----
#pragma unroll
    for (int i = 0; i < 4; i++) {
        float inv = 1.f / l_i[i];
        int row = q0 + 4 * ty + i;
        float* op = out + ((size_t)b * SEQ + row) * VDIM;
        float4 o0, o1;
        o0.x = acc[i][0] * inv; o0.y = acc[i][1] * inv;
        o0.z = acc[i][2] * inv; o0.w = acc[i][3] * inv;
        o1.x = acc[i][4] * inv; o1.y = acc[i][5] * inv;
        o1.z = acc[i][6] * inv; o1.w = acc[i][7] * inv;
        *(float4*)(op + 4 * tx) = o0;
        *(float4*)(op + 64 + 4 * tx) = o1;
    }
}

// =====================================================================
// launcher
// =====================================================================
extern "C" void kernel_launch(void* const* d_in, const int* in_sizes, int n_in,
                              void* d_out, int out_size)
{
    (void)in_sizes; (void)n_in; (void)out_size;
    const float* mem = (const float*)d_in[0];   // [32,1024,200]
    const float* srl = (const float*)d_in[1];   // [32,1024,128]
    const float* emb = (const float*)d_in[2];   // [32,1024,768]
    // d_in[3] word_id_emb: unused by reference
    const float* W1  = (const float*)d_in[4];   // [768,300]
    const float* b1  = (const float*)d_in[5];
    const float* W2  = (const float*)d_in[6];   // [300,200]
    const float* b2  = (const float*)d_in[7];
    const float* mat = (const float*)d_in[8];   // [200,200]
    const float* Wp  = (const float*)d_in[9];   // [128,128]
    const float* bp  = (const float*)d_in[10];
    float* outp = (float*)d_out;                // [32768,128]

    float *h, *qv, *yv, *att;
    cudaGetSymbolAddress((void**)&h,   g_h);
    cudaGetSymbolAddress((void**)&qv,  g_q);
    cudaGetSymbolAddress((void**)&yv,  g_y);
    cudaGetSymbolAddress((void**)&att, g_att);

    cudaFuncSetAttribute(attn_kernel,
                         cudaFuncAttributeMaxDynamicSharedMemorySize,
                         ATTN_SMEM_BYTES);

    // G1: h = relu(emb @ W1 + b1)   [32768,300]
    sgemm128x64<false, true><<<dim3(5, 256), 256>>>(emb, W1, b1, h, MTOT, H1, EMB);
    // G2: q = relu(h @ W2 + b2)     [32768,200]
    sgemm128x64<false, true><<<dim3(4, 256), 256>>>(h, W2, b2, qv, MTOT, DDIM, H1);
    // G3: y = mem @ matrix          [32768,200]
    sgemm128x64<false, false><<<dim3(4, 256), 256>>>(mem, mat, nullptr, yv, MTOT, DDIM, DDIM);
    // fused attention -> att        [32768,128]
    attn_kernel<<<dim3(SEQ / QTILE, BATCH), 512, ATTN_SMEM_BYTES>>>(qv, yv, srl, att);
    // G5: out = att @ Wp^T + bp     [32768,128]
    sgemm128x64<true, false><<<dim3(2, 256), 256>>>(att, Wp, bp, outp, MTOT, VDIM, VDIM);
}

// round 3
// speedup vs baseline: 1.1608x; 1.0821x over previous
#include <cuda_runtime.h>
#include <cstddef>

// Problem constants
#define BATCH 32
#define SEQ   1024
#define VDIM  128
#define EMB   768
#define H1    300
#define DDIM  200
#define MTOT  (BATCH*SEQ)   // 32768

typedef unsigned long long u64;

// ---------------- packed fp32x2 helpers (Blackwell FFMA2 path) ----------------
__device__ __forceinline__ void fma2(u64& c, u64 a, u64 b) {
    asm("fma.rn.f32x2 %0, %1, %2, %0;" : "+l"(c) : "l"(a), "l"(b));
}
__device__ __forceinline__ void mul2(u64& c, u64 a) {
    asm("mul.rn.f32x2 %0, %0, %1;" : "+l"(c) : "l"(a));
}
__device__ __forceinline__ u64 dup2(float x) {
    u64 d; unsigned int u = __float_as_uint(x);
    asm("mov.b64 %0, {%1, %1};" : "=l"(d) : "r"(u));
    return d;
}
__device__ __forceinline__ float2 unpack2(u64 v) {
    unsigned int a, b;
    asm("mov.b64 {%0, %1}, %2;" : "=r"(a), "=r"(b) : "l"(v));
    return make_float2(__uint_as_float(a), __uint_as_float(b));
}

// ---------------- scratch (static device arrays; no allocation) ----------------
__device__ __align__(128) float g_h[(size_t)MTOT * H1];
__device__ __align__(128) float g_q[(size_t)MTOT * DDIM];
__device__ __align__(128) float g_y[(size_t)MTOT * DDIM];
__device__ __align__(128) float g_att[(size_t)MTOT * VDIM];

// =====================================================================
// SGEMM: C[M,N] = act(A[M,K] @ B + bias), FFMA2 inner loop (pack along m)
//   TRANSB=false: B is [K,N] row-major
//   TRANSB=true : B is [N,K] row-major (C = A @ B^T)
// Tile: BM=128, BN=64, BK=16, 256 threads, 8x4 microtile.
// =====================================================================
template<bool TRANSB, bool RELU>
__global__ __launch_bounds__(256) void sgemm128x64(
    const float* __restrict__ A, const float* __restrict__ Bm,
    const float* __restrict__ bias, float* __restrict__ C,
    int M, int N, int K)
{
    __shared__ float As[16 * 132];  // [k][m], padded (132*4=528B, 16B-aligned rows)
    __shared__ float Bs[16 * 68];   // [k][n], padded (68*4=272B, 16B-aligned rows)

    const int tid = threadIdx.x;
    const int tx = tid & 15;
    const int ty = tid >> 4;
    const int m0 = blockIdx.y * 128;
    const int n0 = blockIdx.x * 64;

    // acc2[u][j] packs (row 8ty+2u, row 8ty+2u+1) for column n0+4tx+j
    u64 acc2[4][4];
#pragma unroll
    for (int u = 0; u < 4; u++)
#pragma unroll
        for (int j = 0; j < 4; j++) acc2[u][j] = 0ull;

    const int alm = tid >> 1;
    const int alk = (tid & 1) * 8;
    const int bk  = tid >> 4;
    const int bn4 = (tid & 15) * 4;
    const int btn = tid >> 2;
    const int btk = (tid & 3) * 4;

    for (int k0 = 0; k0 < K; k0 += 16) {
        float4 a0 = make_float4(0.f,0.f,0.f,0.f);
        float4 a1 = a0, bv = a0;
        const float* Arow = A + (size_t)(m0 + alm) * K;
        if (k0 + alk < K)     a0 = *(const float4*)(Arow + k0 + alk);
        if (k0 + alk + 4 < K) a1 = *(const float4*)(Arow + k0 + alk + 4);
        if (TRANSB) {
            if (n0 + btn < N && k0 + btk < K)
                bv = *(const float4*)(Bm + (size_t)(n0 + btn) * K + k0 + btk);
        } else {
            if (k0 + bk < K && n0 + bn4 < N)
                bv = *(const float4*)(Bm + (size_t)(k0 + bk) * N + n0 + bn4);
        }
        __syncthreads();
        As[(alk + 0) * 132 + alm] = a0.x;
        As[(alk + 1) * 132 + alm] = a0.y;
        As[(alk + 2) * 132 + alm] = a0.z;
        As[(alk + 3) * 132 + alm] = a0.w;
        As[(alk + 4) * 132 + alm] = a1.x;
        As[(alk + 5) * 132 + alm] = a1.y;
        As[(alk + 6) * 132 + alm] = a1.z;
        As[(alk + 7) * 132 + alm] = a1.w;
        if (TRANSB) {
            Bs[(btk + 0) * 68 + btn] = bv.x;
            Bs[(btk + 1) * 68 + btn] = bv.y;
            Bs[(btk + 2) * 68 + btn] = bv.z;
            Bs[(btk + 3) * 68 + btn] = bv.w;
        } else {
            *(float4*)(Bs + bk * 68 + bn4) = bv;
        }
        __syncthreads();

#pragma unroll
        for (int k = 0; k < 16; k++) {
            // a pairs along m (contiguous in As) — no packing movs needed
            ulonglong2 a01 = *(const ulonglong2*)(As + k * 132 + 8 * ty);
            ulonglong2 a23 = *(const ulonglong2*)(As + k * 132 + 8 * ty + 4);
            float4 tb = *(const float4*)(Bs + k * 68 + 4 * tx);
            u64 b0 = dup2(tb.x), b1 = dup2(tb.y), b2 = dup2(tb.z), b3 = dup2(tb.w);
            fma2(acc2[0][0], a01.x, b0); fma2(acc2[0][1], a01.x, b1);
            fma2(acc2[0][2], a01.x, b2); fma2(acc2[0][3], a01.x, b3);
            fma2(acc2[1][0], a01.y, b0); fma2(acc2[1][1], a01.y, b1);
            fma2(acc2[1][2], a01.y, b2); fma2(acc2[1][3], a01.y, b3);
            fma2(acc2[2][0], a23.x, b0); fma2(acc2[2][1], a23.x, b1);
            fma2(acc2[2][2], a23.x, b2); fma2(acc2[2][3], a23.x, b3);
            fma2(acc2[3][0], a23.y, b0); fma2(acc2[3][1], a23.y, b1);
            fma2(acc2[3][2], a23.y, b2); fma2(acc2[3][3], a23.y, b3);
        }
    }

    const int nc = n0 + 4 * tx;
    float bb[4] = {0.f, 0.f, 0.f, 0.f};
    if (bias != nullptr && nc < N) {
        float4 t = *(const float4*)(bias + nc);
        bb[0] = t.x; bb[1] = t.y; bb[2] = t.z; bb[3] = t.w;
    }
    if (nc < N) {
#pragma unroll
        for (int u = 0; u < 4; u++) {
            float2 c0 = unpack2(acc2[u][0]);
            float2 c1 = unpack2(acc2[u][1]);
            float2 c2 = unpack2(acc2[u][2]);
            float2 c3 = unpack2(acc2[u][3]);
            float4 olo, ohi;
            olo.x = c0.x + bb[0]; olo.y = c1.x + bb[1];
            olo.z = c2.x + bb[2]; olo.w = c3.x + bb[3];
            ohi.x = c0.y + bb[0]; ohi.y = c1.y + bb[1];
            ohi.z = c2.y + bb[2]; ohi.w = c3.y + bb[3];
            if (RELU) {
                olo.x = fmaxf(olo.x, 0.f); olo.y = fmaxf(olo.y, 0.f);
                olo.z = fmaxf(olo.z, 0.f); olo.w = fmaxf(olo.w, 0.f);
                ohi.x = fmaxf(ohi.x, 0.f); ohi.y = fmaxf(ohi.y, 0.f);
                ohi.z = fmaxf(ohi.z, 0.f); ohi.w = fmaxf(ohi.w, 0.f);
            }
            int rlo = m0 + 8 * ty + 2 * u;
            *(float4*)(C + (size_t)rlo * N + nc) = olo;
            *(float4*)(C + (size_t)(rlo + 1) * N + nc) = ohi;
        }
    }
}

// =====================================================================
// Fused attention: 128 queries x 64 keys per CTA, 512 threads, FFMA2.
// Thread grid 16(tx) x 32(ty):
//   q rows = 4*ty+i (i<4, contiguous)    s cols = tx+16*j (j<4)
//   out cols v = 4tx..4tx+3 and 64+4tx..64+4tx+3 (packed pairs)
// =====================================================================
#define QTILE 128
#define STILE 64
#define QS_STRIDE  204
#define YS_STRIDE  204
#define SRL_STRIDE 132
#define PS_STRIDE  132
#define ATTN_SMEM_FLOATS (QTILE*QS_STRIDE + STILE*YS_STRIDE + STILE*SRL_STRIDE + STILE*PS_STRIDE)
#define ATTN_SMEM_BYTES  (ATTN_SMEM_FLOATS * 4)   // 224,256 B

__global__ __launch_bounds__(512) void attn_kernel(
    const float* __restrict__ q,    // [B,S,200]
    const float* __restrict__ y,    // [B,S,200]
    const float* __restrict__ srl,  // [B,S,128]
    float* __restrict__ out)        // [B,S,128]
{
    extern __shared__ float sm[];
    float* qs   = sm;                        // [128][204]
    float* ys   = qs   + QTILE * QS_STRIDE;  // [64][204]
    float* srls = ys   + STILE * YS_STRIDE;  // [64][132]
    float* ps   = srls + STILE * SRL_STRIDE; // ps[s][q] : [64][132]

    const int tid = threadIdx.x;
    const int tx = tid & 15;
    const int ty = tid >> 4;         // 0..31
    const int b  = blockIdx.y;
    const int q0 = blockIdx.x * QTILE;

    const float* qb = q   + ((size_t)b * SEQ + q0) * DDIM;
    const float* yb = y   + (size_t)b * SEQ * DDIM;
    const float* sb = srl + (size_t)b * SEQ * VDIM;

    for (int idx = tid; idx < QTILE * 50; idx += 512) {
        int r = idx / 50, c = (idx % 50) * 4;
        *(float4*)(qs + r * QS_STRIDE + c) = *(const float4*)(qb + (size_t)r * DDIM + c);
    }

    float m_i[4], l_i[4];
    u64 acc2[4][4];   // [i][g]: g=0:(v,v+1)@4tx  g=1:(v+2,v+3)  g=2,3: +64
#pragma unroll
    for (int i = 0; i < 4; i++) {
        m_i[i] = -1e30f; l_i[i] = 0.f;
#pragma unroll
        for (int g = 0; g < 4; g++) acc2[i][g] = 0ull;
    }

    for (int s0 = 0; s0 < SEQ; s0 += STILE) {
        __syncthreads();
        for (int idx = tid; idx < STILE * 50; idx += 512) {
            int r = idx / 50, c = (idx % 50) * 4;
            *(float4*)(ys + r * YS_STRIDE + c) =
                *(const float4*)(yb + (size_t)(s0 + r) * DDIM + c);
        }
        for (int idx = tid; idx < STILE * 32; idx += 512) {
            int r = idx >> 5, c = (idx & 31) * 4;
            *(float4*)(srls + r * SRL_STRIDE + c) =
                *(const float4*)(sb + (size_t)(s0 + r) * VDIM + c);
        }
        __syncthreads();

        // ---- scores: packed along k, halves summed at the end ----
        u64 sc2[4][4];
#pragma unroll
        for (int i = 0; i < 4; i++)
#pragma unroll
            for (int j = 0; j < 4; j++) sc2[i][j] = 0ull;

#pragma unroll 2
        for (int kk = 0; kk < DDIM; kk += 4) {
            ulonglong2 aq2[4], ay2[4];
#pragma unroll
            for (int i = 0; i < 4; i++)
                aq2[i] = *(const ulonglong2*)(qs + (4 * ty + i) * QS_STRIDE + kk);
#pragma unroll
            for (int j = 0; j < 4; j++)
                ay2[j] = *(const ulonglong2*)(ys + (tx + 16 * j) * YS_STRIDE + kk);
#pragma unroll
            for (int i = 0; i < 4; i++)
#pragma unroll
                for (int j = 0; j < 4; j++) {
                    fma2(sc2[i][j], aq2[i].x, ay2[j].x);
                    fma2(sc2[i][j], aq2[i].y, ay2[j].y);
                }
        }

        float sc[4][4];
#pragma unroll
        for (int i = 0; i < 4; i++)
#pragma unroll
            for (int j = 0; j < 4; j++) {
                float2 h = unpack2(sc2[i][j]);
                sc[i][j] = h.x + h.y;
            }

        // ---- online softmax update (reduce across 16 tx lanes in-warp) ----
        float p[4][4];
#pragma unroll
        for (int i = 0; i < 4; i++) {
            float tm = fmaxf(fmaxf(sc[i][0], sc[i][1]), fmaxf(sc[i][2], sc[i][3]));
            tm = fmaxf(tm, __shfl_xor_sync(0xffffffffu, tm, 1));
            tm = fmaxf(tm, __shfl_xor_sync(0xffffffffu, tm, 2));
            tm = fmaxf(tm, __shfl_xor_sync(0xffffffffu, tm, 4));
            tm = fmaxf(tm, __shfl_xor_sync(0xffffffffu, tm, 8));
            float mn = fmaxf(m_i[i], tm);
            float ts = 0.f;
#pragma unroll
            for (int j = 0; j < 4; j++) { p[i][j] = __expf(sc[i][j] - mn); ts += p[i][j]; }
            ts += __shfl_xor_sync(0xffffffffu, ts, 1);
            ts += __shfl_xor_sync(0xffffffffu, ts, 2);
            ts += __shfl_xor_sync(0xffffffffu, ts, 4);
            ts += __shfl_xor_sync(0xffffffffu, ts, 8);
            float f = __expf(m_i[i] - mn);
            l_i[i] = l_i[i] * f + ts;
            m_i[i] = mn;
            u64 ff = dup2(f);
#pragma unroll
            for (int g = 0; g < 4; g++) mul2(acc2[i][g], ff);
        }

        // ---- write P transposed: ps[s][q], q contiguous ----
#pragma unroll
        for (int j = 0; j < 4; j++)
#pragma unroll
            for (int i = 0; i < 4; i++)
                ps[(tx + 16 * j) * PS_STRIDE + (4 * ty + i)] = p[i][j];
        __syncthreads();

        // ---- PV: acc[q][v] += P[q][s] * srl[s][v], packed along v ----
#pragma unroll 4
        for (int s = 0; s < STILE; s++) {
            float4 rp = *(const float4*)(ps + s * PS_STRIDE + 4 * ty);
            ulonglong2 r0 = *(const ulonglong2*)(srls + s * SRL_STRIDE + 4 * tx);
            ulonglong2 r1 = *(const ulonglong2*)(srls + s * SRL_STRIDE + 64 + 4 * tx);
            u64 d0 = dup2(rp.x), d1 = dup2(rp.y), d2 = dup2(rp.z), d3 = dup2(rp.w);
            fma2(acc2[0][0], d0, r0.x); fma2(acc2[0][1], d0, r0.y);
            fma2(acc2[0][2], d0, r1.x); fma2(acc2[0][3], d0, r1.y);
            fma2(acc2[1][0], d1, r0.x); fma2(acc2[1][1], d1, r0.y);
            fma2(acc2[1][2], d1, r1.x); fma2(acc2[1][3], d1, r1.y);
            fma2(acc2[2][0], d2, r0.x); fma2(acc2[2][1], d2, r0.y);
            fma2(acc2[2][2], d2, r1.x); fma2(acc2[2][3], d2, r1.y);
            fma2(acc2[3][0], d3, r0.x); fma2(acc2[3][1], d3, r0.y);
            fma2(acc2[3][2], d3, r1.x); fma2(acc2[3][3], d3, r1.y);
        }
    }

    // ---- normalize + store ----
#pragma unroll
    for (int i = 0; i < 4; i++) {
        float inv = 1.f / l_i[i];
        int row = q0 + 4 * ty + i;
        float* op = out + ((size_t)b * SEQ + row) * VDIM;
        float2 u0 = unpack2(acc2[i][0]);
        float2 u1 = unpack2(acc2[i][1]);
        float2 u2 = unpack2(acc2[i][2]);
        float2 u3 = unpack2(acc2[i][3]);
        float4 o0, o1;
        o0.x = u0.x * inv; o0.y = u0.y * inv; o0.z = u1.x * inv; o0.w = u1.y * inv;
        o1.x = u2.x * inv; o1.y = u2.y * inv; o1.z = u3.x * inv; o1.w = u3.y * inv;
        *(float4*)(op + 4 * tx) = o0;
        *(float4*)(op + 64 + 4 * tx) = o1;
    }
}

// =====================================================================
// launcher
// =====================================================================
extern "C" void kernel_launch(void* const* d_in, const int* in_sizes, int n_in,
                              void* d_out, int out_size)
{
    (void)in_sizes; (void)n_in; (void)out_size;
    const float* mem = (const float*)d_in[0];   // [32,1024,200]
    const float* srl = (const float*)d_in[1];   // [32,1024,128]
    const float* emb = (const float*)d_in[2];   // [32,1024,768]
    const float* W1  = (const float*)d_in[4];   // [768,300]
    const float* b1  = (const float*)d_in[5];
    const float* W2  = (const float*)d_in[6];   // [300,200]
    const float* b2  = (const float*)d_in[7];
    const float* mat = (const float*)d_in[8];   // [200,200]
    const float* Wp  = (const float*)d_in[9];   // [128,128]
    const float* bp  = (const float*)d_in[10];
    float* outp = (float*)d_out;                // [32768,128]

    float *h, *qv, *yv, *att;
    cudaGetSymbolAddress((void**)&h,   g_h);
    cudaGetSymbolAddress((void**)&qv,  g_q);
    cudaGetSymbolAddress((void**)&yv,  g_y);
    cudaGetSymbolAddress((void**)&att, g_att);

    cudaFuncSetAttribute(attn_kernel,
                         cudaFuncAttributeMaxDynamicSharedMemorySize,
                         ATTN_SMEM_BYTES);

    // G1: h = relu(emb @ W1 + b1)   [32768,300]
    sgemm128x64<false, true><<<dim3(5, 256), 256>>>(emb, W1, b1, h, MTOT, H1, EMB);
    // G2: q = relu(h @ W2 + b2)     [32768,200]
    sgemm128x64<false, true><<<dim3(4, 256), 256>>>(h, W2, b2, qv, MTOT, DDIM, H1);
    // G3: y = mem @ matrix          [32768,200]
    sgemm128x64<false, false><<<dim3(4, 256), 256>>>(mem, mat, nullptr, yv, MTOT, DDIM, DDIM);
    // fused attention -> att        [32768,128]
    attn_kernel<<<dim3(SEQ / QTILE, BATCH), 512, ATTN_SMEM_BYTES>>>(qv, yv, srl, att);
    // G5: out = att @ Wp^T + bp     [32768,128]
    sgemm128x64<true, false><<<dim3(2, 256), 256>>>(att, Wp, bp, outp, MTOT, VDIM, VDIM);
}

// round 5
// speedup vs baseline: 1.1903x; 1.0255x over previous
#include <cuda_runtime.h>
#include <cuda_bf16.h>
#include <cstdint>
#include <cstddef>

// Problem constants
#define BATCH 32
#define SEQ   1024
#define VDIM  128
#define EMB   768
#define H1    300
#define DDIM  200
#define MTOT  (BATCH*SEQ)   // 32768

typedef unsigned long long u64;

// ---------------- packed fp32x2 helpers (attention kernel) ----------------
__device__ __forceinline__ void fma2(u64& c, u64 a, u64 b) {
    asm("fma.rn.f32x2 %0, %1, %2, %0;" : "+l"(c) : "l"(a), "l"(b));
}
__device__ __forceinline__ void mul2(u64& c, u64 a) {
    asm("mul.rn.f32x2 %0, %0, %1;" : "+l"(c) : "l"(a));
}
__device__ __forceinline__ u64 dup2(float x) {
    u64 d; unsigned int u = __float_as_uint(x);
    asm("mov.b64 %0, {%1, %1};" : "=l"(d) : "r"(u));
    return d;
}
__device__ __forceinline__ float2 unpack2(u64 v) {
    unsigned int a, b;
    asm("mov.b64 {%0, %1}, %2;" : "=r"(a), "=r"(b) : "l"(v));
    return make_float2(__uint_as_float(a), __uint_as_float(b));
}

// ---------------- bf16 split helpers ----------------
__device__ __forceinline__ uint32_t pack_bf16(__nv_bfloat16 lo16, __nv_bfloat16 hi16) {
    __nv_bfloat162 t(lo16, hi16);
    return *(uint32_t*)&t;
}
__device__ __forceinline__ void split_bf16(float v, __nv_bfloat16& h, __nv_bfloat16& l) {
    h = __float2bfloat16(v);
    l = __float2bfloat16(v - __bfloat162float(h));
}

// mma.sync m16n8k16 bf16: D += A*B  (row.col)
__device__ __forceinline__ void mma16816(float* d, const uint32_t* a, const uint32_t* b) {
    asm volatile(
        "mma.sync.aligned.m16n8k16.row.col.f32.bf16.bf16.f32 "
        "{%0,%1,%2,%3}, {%4,%5,%6,%7}, {%8,%9}, {%0,%1,%2,%3};"
        : "+f"(d[0]), "+f"(d[1]), "+f"(d[2]), "+f"(d[3])
        : "r"(a[0]), "r"(a[1]), "r"(a[2]), "r"(a[3]), "r"(b[0]), "r"(b[1]));
}

// ---------------- scratch (static device arrays; no allocation) ----------------
__device__ __align__(128) float g_h[(size_t)MTOT * H1];
__device__ __align__(128) float g_q[(size_t)MTOT * DDIM];
__device__ __align__(128) float g_y[(size_t)MTOT * DDIM];
__device__ __align__(128) float g_att[(size_t)MTOT * VDIM];

// =====================================================================
// mma.sync bf16x3-split GEMM: C[M,N] = act(A[M,K] @ B + bias)
//   TRANSB=false: B is [K,N] row-major;  TRANSB=true: B is [N,K] (C=A@B^T)
// CTA tile 128(M) x 128(N), K-chunk 32 fp32. 256 threads = 8 warps (2m x 4n),
// warp tile 64x32, mma m16n8k16: 4 m-frags x 4 n-frags, 3 mma per pair
// (ah*bh + al*bh + ah*bl). SMEM: 4 tiles [128 rows][40 bf16 stride] = 40KB.
// Row stride 20 words makes all fragment LDS conflict-free:
// bank(row,word c) = (20*row + c) % 32 — distinct for g=0..7, c=0..3.
// =====================================================================
#define GSTRIDE_W 20   // words per smem row (16 data + 4 pad)

template<bool TRANSB, bool RELU>
__global__ __launch_bounds__(256) void gemm_mma(
    const float* __restrict__ A, const float* __restrict__ Bm,
    const float* __restrict__ bias, float* __restrict__ C,
    int M, int N, int K)
{
    __shared__ uint32_t smw[4 * 128 * GSTRIDE_W];   // Ah | Al | Bh | Bl  (40KB)
    uint32_t* sAh = smw;
    uint32_t* sAl = smw + 2560;
    uint32_t* sBh = smw + 5120;
    uint32_t* sBl = smw + 7680;

    const int tid  = threadIdx.x;
    const int wid  = tid >> 5;
    const int lane = tid & 31;
    const int g    = lane >> 2;    // 0..7
    const int c    = lane & 3;     // 0..3
    const int wm   = wid & 1;      // 0..1 (m warp)
    const int wn   = wid >> 1;     // 0..3 (n warp)
    const int m0 = blockIdx.y * 128;
    const int n0 = blockIdx.x * 128;

    float acc[4][4][4];
#pragma unroll
    for (int mi = 0; mi < 4; mi++)
#pragma unroll
        for (int ni = 0; ni < 4; ni++)
#pragma unroll
            for (int r = 0; r < 4; r++) acc[mi][ni][r] = 0.f;

    for (int k0 = 0; k0 < K; k0 += 32) {
        __syncthreads();   // previous chunk's compute done reading smem

        // ---- A chunk: 128 rows x 32 k fp32 -> (Ah|Al) ----
#pragma unroll
        for (int p = 0; p < 4; p++) {
            int f4  = tid + 256 * p;
            int row = f4 >> 3;
            int kc  = (f4 & 7) << 2;
            float4 v = make_float4(0.f, 0.f, 0.f, 0.f);
            if (k0 + kc < K)
                v = *(const float4*)(A + (size_t)(m0 + row) * K + k0 + kc);
            __nv_bfloat16 h0, h1, h2, h3, l0, l1, l2, l3;
            split_bf16(v.x, h0, l0); split_bf16(v.y, h1, l1);
            split_bf16(v.z, h2, l2); split_bf16(v.w, h3, l3);
            int w = row * GSTRIDE_W + (kc >> 1);
            sAh[w]     = pack_bf16(h0, h1);
            sAh[w + 1] = pack_bf16(h2, h3);
            sAl[w]     = pack_bf16(l0, l1);
            sAl[w + 1] = pack_bf16(l2, l3);
        }

        // ---- B chunk -> (Bh|Bl), smem layout [n][k] (k contiguous) ----
        if (TRANSB) {
            // B is [N,K]: rows are already [n][k]
#pragma unroll
            for (int p = 0; p < 4; p++) {
                int f4  = tid + 256 * p;
                int row = f4 >> 3;         // n
                int kc  = (f4 & 7) << 2;
                float4 v = make_float4(0.f, 0.f, 0.f, 0.f);
                if (n0 + row < N && k0 + kc < K)
                    v = *(const float4*)(Bm + (size_t)(n0 + row) * K + k0 + kc);
                __nv_bfloat16 h0, h1, h2, h3, l0, l1, l2, l3;
                split_bf16(v.x, h0, l0); split_bf16(v.y, h1, l1);
                split_bf16(v.z, h2, l2); split_bf16(v.w, h3, l3);
                int w = row * GSTRIDE_W + (kc >> 1);
                sBh[w]     = pack_bf16(h0, h1);
                sBh[w + 1] = pack_bf16(h2, h3);
                sBl[w]     = pack_bf16(l0, l1);
                sBl[w + 1] = pack_bf16(l2, l3);
            }
        } else {
            // B is [K,N]: transpose through registers (coalesced gmem reads)
            const int n  = tid & 127;
            const int kr = tid >> 7;       // 0..1
            const bool nok = (n0 + n) < N;
            __nv_bfloat16* bh16 = (__nv_bfloat16*)sBh;
            __nv_bfloat16* bl16 = (__nv_bfloat16*)sBl;
#pragma unroll
            for (int p = 0; p < 16; p++) {
                int k = kr + 2 * p;
                float v = 0.f;
                if (nok && (k0 + k) < K)
                    v = Bm[(size_t)(k0 + k) * N + n0 + n];
                __nv_bfloat16 h, l;
                split_bf16(v, h, l);
                bh16[n * (2 * GSTRIDE_W) + k] = h;
                bl16[n * (2 * GSTRIDE_W) + k] = l;
            }
        }

        __syncthreads();

        // ---- compute: 2 k16 steps ----
#pragma unroll
        for (int ks = 0; ks < 2; ks++) {
            const int kw = ks * 8;    // word offset of this k16 within a row
            uint32_t bh[4][2], bl[4][2];
#pragma unroll
            for (int ni = 0; ni < 4; ni++) {
                int base = (wn * 32 + ni * 8 + g) * GSTRIDE_W + kw + c;
                bh[ni][0] = sBh[base]; bh[ni][1] = sBh[base + 4];
                bl[ni][0] = sBl[base]; bl[ni][1] = sBl[base + 4];
            }
#pragma unroll
            for (int mi = 0; mi < 4; mi++) {
                int base = (wm * 64 + mi * 16 + g) * GSTRIDE_W + kw + c;
                uint32_t ah[4], al[4];
                ah[0] = sAh[base];       ah[1] = sAh[base + 8 * GSTRIDE_W];
                ah[2] = sAh[base + 4];   ah[3] = sAh[base + 4 + 8 * GSTRIDE_W];
                al[0] = sAl[base];       al[1] = sAl[base + 8 * GSTRIDE_W];
                al[2] = sAl[base + 4];   al[3] = sAl[base + 4 + 8 * GSTRIDE_W];
#pragma unroll
                for (int ni = 0; ni < 4; ni++) {
                    mma16816(acc[mi][ni], ah, bh[ni]);
                    mma16816(acc[mi][ni], al, bh[ni]);
                    mma16816(acc[mi][ni], ah, bl[ni]);
                }
            }
        }
    }

    // ---- epilogue: bias + relu + store (float2 per fragment row) ----
#pragma unroll
    for (int mi = 0; mi < 4; mi++) {
#pragma unroll
        for (int ni = 0; ni < 4; ni++) {
            int row = m0 + wm * 64 + mi * 16 + g;
            int col = n0 + wn * 32 + ni * 8 + 2 * c;
            if (col < N) {
                float bx = 0.f, by = 0.f;
                if (bias != nullptr) { bx = bias[col]; by = bias[col + 1]; }
                float2 o0, o1;
                o0.x = acc[mi][ni][0] + bx; o0.y = acc[mi][ni][1] + by;
                o1.x = acc[mi][ni][2] + bx; o1.y = acc[mi][ni][3] + by;
                if (RELU) {
                    o0.x = fmaxf(o0.x, 0.f); o0.y = fmaxf(o0.y, 0.f);
                    o1.x = fmaxf(o1.x, 0.f); o1.y = fmaxf(o1.y, 0.f);
                }
                *(float2*)(C + (size_t)row * N + col) = o0;
                *(float2*)(C + (size_t)(row + 8) * N + col) = o1;
            }
        }
    }
}

// =====================================================================
// Fused attention: 128 queries x 64 keys per CTA, 512 threads, FFMA2.
// (unchanged from round 3)
// =====================================================================
#define QTILE 128
#define STILE 64
#define QS_STRIDE  204
#define YS_STRIDE  204
#define SRL_STRIDE 132
#define PS_STRIDE  132
#define ATTN_SMEM_FLOATS (QTILE*QS_STRIDE + STILE*YS_STRIDE + STILE*SRL_STRIDE + STILE*PS_STRIDE)
#define ATTN_SMEM_BYTES  (ATTN_SMEM_FLOATS * 4)   // 224,256 B

__global__ __launch_bounds__(512) void attn_kernel(
    const float* __restrict__ q,    // [B,S,200]
    const float* __restrict__ y,    // [B,S,200]
    const float* __restrict__ srl,  // [B,S,128]
    float* __restrict__ out)        // [B,S,128]
{
    extern __shared__ float sm[];
    float* qs   = sm;                        // [128][204]
    float* ys   = qs   + QTILE * QS_STRIDE;  // [64][204]
    float* srls = ys   + STILE * YS_STRIDE;  // [64][132]
    float* ps   = srls + STILE * SRL_STRIDE; // ps[s][q] : [64][132]

    const int tid = threadIdx.x;
    const int tx = tid & 15;
    const int ty = tid >> 4;         // 0..31
    const int b  = blockIdx.y;
    const int q0 = blockIdx.x * QTILE;

    const float* qb = q   + ((size_t)b * SEQ + q0) * DDIM;
    const float* yb = y   + (size_t)b * SEQ * DDIM;
    const float* sb = srl + (size_t)b * SEQ * VDIM;

    for (int idx = tid; idx < QTILE * 50; idx += 512) {
        int r = idx / 50, c = (idx % 50) * 4;
        *(float4*)(qs + r * QS_STRIDE + c) = *(const float4*)(qb + (size_t)r * DDIM + c);
    }

    float m_i[4], l_i[4];
    u64 acc2[4][4];
#pragma unroll
    for (int i = 0; i < 4; i++) {
        m_i[i] = -1e30f; l_i[i] = 0.f;
#pragma unroll
        for (int g = 0; g < 4; g++) acc2[i][g] = 0ull;
    }

    for (int s0 = 0; s0 < SEQ; s0 += STILE) {
        __syncthreads();
        for (int idx = tid; idx < STILE * 50; idx += 512) {
            int r = idx / 50, c = (idx % 50) * 4;
            *(float4*)(ys + r * YS_STRIDE + c) =
                *(const float4*)(yb + (size_t)(s0 + r) * DDIM + c);
        }
        for (int idx = tid; idx < STILE * 32; idx += 512) {
            int r = idx >> 5, c = (idx & 31) * 4;
            *(float4*)(srls + r * SRL_STRIDE + c) =
                *(const float4*)(sb + (size_t)(s0 + r) * VDIM + c);
        }
        __syncthreads();

        u64 sc2[4][4];
#pragma unroll
        for (int i = 0; i < 4; i++)
#pragma unroll
            for (int j = 0; j < 4; j++) sc2[i][j] = 0ull;

#pragma unroll 2
        for (int kk = 0; kk < DDIM; kk += 4) {
            ulonglong2 aq2[4], ay2[4];
#pragma unroll
            for (int i = 0; i < 4; i++)
                aq2[i] = *(const ulonglong2*)(qs + (4 * ty + i) * QS_STRIDE + kk);
#pragma unroll
            for (int j = 0; j < 4; j++)
                ay2[j] = *(const ulonglong2*)(ys + (tx + 16 * j) * YS_STRIDE + kk);
#pragma unroll
            for (int i = 0; i < 4; i++)
#pragma unroll
                for (int j = 0; j < 4; j++) {
                    fma2(sc2[i][j], aq2[i].x, ay2[j].x);
                    fma2(sc2[i][j], aq2[i].y, ay2[j].y);
                }
        }

        float sc[4][4];
#pragma unroll
        for (int i = 0; i < 4; i++)
#pragma unroll
            for (int j = 0; j < 4; j++) {
                float2 h = unpack2(sc2[i][j]);
                sc[i][j] = h.x + h.y;
            }

        float p[4][4];
#pragma unroll
        for (int i = 0; i < 4; i++) {
            float tm = fmaxf(fmaxf(sc[i][0], sc[i][1]), fmaxf(sc[i][2], sc[i][3]));
            tm = fmaxf(tm, __shfl_xor_sync(0xffffffffu, tm, 1));
            tm = fmaxf(tm, __shfl_xor_sync(0xffffffffu, tm, 2));
            tm = fmaxf(tm, __shfl_xor_sync(0xffffffffu, tm, 4));
            tm = fmaxf(tm, __shfl_xor_sync(0xffffffffu, tm, 8));
            float mn = fmaxf(m_i[i], tm);
            float ts = 0.f;
#pragma unroll
            for (int j = 0; j < 4; j++) { p[i][j] = __expf(sc[i][j] - mn); ts += p[i][j]; }
            ts += __shfl_xor_sync(0xffffffffu, ts, 1);
            ts += __shfl_xor_sync(0xffffffffu, ts, 2);
            ts += __shfl_xor_sync(0xffffffffu, ts, 4);
            ts += __shfl_xor_sync(0xffffffffu, ts, 8);
            float f = __expf(m_i[i] - mn);
            l_i[i] = l_i[i] * f + ts;
            m_i[i] = mn;
            u64 ff = dup2(f);
#pragma unroll
            for (int g = 0; g < 4; g++) mul2(acc2[i][g], ff);
        }

#pragma unroll
        for (int j = 0; j < 4; j++)
#pragma unroll
            for (int i = 0; i < 4; i++)
                ps[(tx + 16 * j) * PS_STRIDE + (4 * ty + i)] = p[i][j];
        __syncthreads();

#pragma unroll 4
        for (int s = 0; s < STILE; s++) {
            float4 rp = *(const float4*)(ps + s * PS_STRIDE + 4 * ty);
            ulonglong2 r0 = *(const ulonglong2*)(srls + s * SRL_STRIDE + 4 * tx);
            ulonglong2 r1 = *(const ulonglong2*)(srls + s * SRL_STRIDE + 64 + 4 * tx);
            u64 d0 = dup2(rp.x), d1 = dup2(rp.y), d2 = dup2(rp.z), d3 = dup2(rp.w);
            fma2(acc2[0][0], d0, r0.x); fma2(acc2[0][1], d0, r0.y);
            fma2(acc2[0][2], d0, r1.x); fma2(acc2[0][3], d0, r1.y);
            fma2(acc2[1][0], d1, r0.x); fma2(acc2[1][1], d1, r0.y);
            fma2(acc2[1][2], d1, r1.x); fma2(acc2[1][3], d1, r1.y);
            fma2(acc2[2][0], d2, r0.x); fma2(acc2[2][1], d2, r0.y);
            fma2(acc2[2][2], d2, r1.x); fma2(acc2[2][3], d2, r1.y);
            fma2(acc2[3][0], d3, r0.x); fma2(acc2[3][1], d3, r0.y);
            fma2(acc2[3][2], d3, r1.x); fma2(acc2[3][3], d3, r1.y);
        }
    }

#pragma unroll
    for (int i = 0; i < 4; i++) {
        float inv = 1.f / l_i[i];
        int row = q0 + 4 * ty + i;
        float* op = out + ((size_t)b * SEQ + row) * VDIM;
        float2 u0 = unpack2(acc2[i][0]);
        float2 u1 = unpack2(acc2[i][1]);
        float2 u2 = unpack2(acc2[i][2]);
        float2 u3 = unpack2(acc2[i][3]);
        float4 o0, o1;
        o0.x = u0.x * inv; o0.y = u0.y * inv; o0.z = u1.x * inv; o0.w = u1.y * inv;
        o1.x = u2.x * inv; o1.y = u2.y * inv; o1.z = u3.x * inv; o1.w = u3.y * inv;
        *(float4*)(op + 4 * tx) = o0;
        *(float4*)(op + 64 + 4 * tx) = o1;
    }
}

// =====================================================================
// launcher
// =====================================================================
extern "C" void kernel_launch(void* const* d_in, const int* in_sizes, int n_in,
                              void* d_out, int out_size)
{
    (void)in_sizes; (void)n_in; (void)out_size;
    const float* mem = (const float*)d_in[0];   // [32,1024,200]
    const float* srl = (const float*)d_in[1];   // [32,1024,128]
    const float* emb = (const float*)d_in[2];   // [32,1024,768]
    const float* W1  = (const float*)d_in[4];   // [768,300]
    const float* b1  = (const float*)d_in[5];
    const float* W2  = (const float*)d_in[6];   // [300,200]
    const float* b2  = (const float*)d_in[7];
    const float* mat = (const float*)d_in[8];   // [200,200]
    const float* Wp  = (const float*)d_in[9];   // [128,128]
    const float* bp  = (const float*)d_in[10];
    float* outp = (float*)d_out;                // [32768,128]

    float *h, *qv, *yv, *att;
    cudaGetSymbolAddress((void**)&h,   g_h);
    cudaGetSymbolAddress((void**)&qv,  g_q);
    cudaGetSymbolAddress((void**)&yv,  g_y);
    cudaGetSymbolAddress((void**)&att, g_att);

    cudaFuncSetAttribute(attn_kernel,
                         cudaFuncAttributeMaxDynamicSharedMemorySize, ATTN_SMEM_BYTES);

    // G1: h = relu(emb @ W1 + b1)   [32768,300]   N-tiles: 3
    gemm_mma<false, true><<<dim3(3, 256), 256>>>(emb, W1, b1, h, MTOT, H1, EMB);
    // G2: q = relu(h @ W2 + b2)     [32768,200]   N-tiles: 2
    gemm_mma<false, true><<<dim3(2, 256), 256>>>(h, W2, b2, qv, MTOT, DDIM, H1);
    // G3: y = mem @ matrix          [32768,200]   N-tiles: 2
    gemm_mma<false, false><<<dim3(2, 256), 256>>>(mem, mat, nullptr, yv, MTOT, DDIM, DDIM);
    // fused attention -> att        [32768,128]
    attn_kernel<<<dim3(SEQ / QTILE, BATCH), 512, ATTN_SMEM_BYTES>>>(qv, yv, srl, att);
    // G5: out = att @ Wp^T + bp     [32768,128]   N-tiles: 1
    gemm_mma<true, false><<<dim3(1, 256), 256>>>(att, Wp, bp, outp, MTOT, VDIM, VDIM);
}

// round 6
// speedup vs baseline: 1.7427x; 1.4641x over previous
#include <cuda_runtime.h>
#include <cuda_bf16.h>
#include <cstdint>
#include <cstddef>

// Problem constants
#define BATCH 32
#define SEQ   1024
#define VDIM  128
#define EMB   768
#define H1    300
#define DDIM  200
#define MTOT  (BATCH*SEQ)   // 32768

// ---------------- bf16 split helpers ----------------
__device__ __forceinline__ uint32_t pack_bf16(__nv_bfloat16 lo16, __nv_bfloat16 hi16) {
    __nv_bfloat162 t(lo16, hi16);
    return *(uint32_t*)&t;
}
__device__ __forceinline__ void split_bf16(float v, __nv_bfloat16& h, __nv_bfloat16& l) {
    h = __float2bfloat16(v);
    l = __float2bfloat16(v - __bfloat162float(h));
}
// split a float pair -> (hi packed, lo packed); .x of bf16x2 = first (low) element
__device__ __forceinline__ void split_pack2(float x, float y, uint32_t& hi, uint32_t& lo) {
    __nv_bfloat16 hx, lx, hy, ly;
    split_bf16(x, hx, lx);
    split_bf16(y, hy, ly);
    hi = pack_bf16(hx, hy);
    lo = pack_bf16(lx, ly);
}

// mma.sync m16n8k16 bf16: D += A*B  (row.col)
__device__ __forceinline__ void mma16816(float* d, const uint32_t* a, const uint32_t* b) {
    asm volatile(
        "mma.sync.aligned.m16n8k16.row.col.f32.bf16.bf16.f32 "
        "{%0,%1,%2,%3}, {%4,%5,%6,%7}, {%8,%9}, {%0,%1,%2,%3};"
        : "+f"(d[0]), "+f"(d[1]), "+f"(d[2]), "+f"(d[3])
        : "r"(a[0]), "r"(a[1]), "r"(a[2]), "r"(a[3]), "r"(b[0]), "r"(b[1]));
}
__device__ __forceinline__ void mma2(float* d, const uint32_t* a, uint32_t b0, uint32_t b1) {
    asm volatile(
        "mma.sync.aligned.m16n8k16.row.col.f32.bf16.bf16.f32 "
        "{%0,%1,%2,%3}, {%4,%5,%6,%7}, {%8,%9}, {%0,%1,%2,%3};"
        : "+f"(d[0]), "+f"(d[1]), "+f"(d[2]), "+f"(d[3])
        : "r"(a[0]), "r"(a[1]), "r"(a[2]), "r"(a[3]), "r"(b0), "r"(b1));
}

__device__ __forceinline__ uint32_t smem_u32(const void* p) {
    uint32_t a;
    asm("{ .reg .u64 t; cvta.to.shared.u64 t, %1; cvt.u32.u64 %0, t; }"
        : "=r"(a) : "l"(p));
    return a;
}
__device__ __forceinline__ void ldmx4(uint32_t* r, uint32_t addr) {
    asm volatile("ldmatrix.sync.aligned.m8n8.x4.shared.b16 {%0,%1,%2,%3}, [%4];"
        : "=r"(r[0]), "=r"(r[1]), "=r"(r[2]), "=r"(r[3]) : "r"(addr));
}
__device__ __forceinline__ void ldmx4t(uint32_t* r, uint32_t addr) {
    asm volatile("ldmatrix.sync.aligned.m8n8.x4.trans.shared.b16 {%0,%1,%2,%3}, [%4];"
        : "=r"(r[0]), "=r"(r[1]), "=r"(r[2]), "=r"(r[3]) : "r"(addr));
}

// ---------------- scratch (static device arrays; no allocation) ----------------
__device__ __align__(128) float g_h[(size_t)MTOT * H1];
__device__ __align__(128) float g_q[(size_t)MTOT * DDIM];
__device__ __align__(128) float g_y[(size_t)MTOT * DDIM];
__device__ __align__(128) float g_att[(size_t)MTOT * VDIM];

// =====================================================================
// mma.sync bf16x3-split GEMM (unchanged from round 5, passing)
// =====================================================================
#define GSTRIDE_W 20   // words per smem row (16 data + 4 pad)

template<bool TRANSB, bool RELU>
__global__ __launch_bounds__(256) void gemm_mma(
    const float* __restrict__ A, const float* __restrict__ Bm,
    const float* __restrict__ bias, float* __restrict__ C,
    int M, int N, int K)
{
    __shared__ uint32_t smw[4 * 128 * GSTRIDE_W];   // Ah | Al | Bh | Bl  (40KB)
    uint32_t* sAh = smw;
    uint32_t* sAl = smw + 2560;
    uint32_t* sBh = smw + 5120;
    uint32_t* sBl = smw + 7680;

    const int tid  = threadIdx.x;
    const int wid  = tid >> 5;
    const int lane = tid & 31;
    const int g    = lane >> 2;
    const int c    = lane & 3;
    const int wm   = wid & 1;
    const int wn   = wid >> 1;
    const int m0 = blockIdx.y * 128;
    const int n0 = blockIdx.x * 128;

    float acc[4][4][4];
#pragma unroll
    for (int mi = 0; mi < 4; mi++)
#pragma unroll
        for (int ni = 0; ni < 4; ni++)
#pragma unroll
            for (int r = 0; r < 4; r++) acc[mi][ni][r] = 0.f;

    for (int k0 = 0; k0 < K; k0 += 32) {
        __syncthreads();

#pragma unroll
        for (int p = 0; p < 4; p++) {
            int f4  = tid + 256 * p;
            int row = f4 >> 3;
            int kc  = (f4 & 7) << 2;
            float4 v = make_float4(0.f, 0.f, 0.f, 0.f);
            if (k0 + kc < K)
                v = *(const float4*)(A + (size_t)(m0 + row) * K + k0 + kc);
            __nv_bfloat16 h0, h1, h2, h3, l0, l1, l2, l3;
            split_bf16(v.x, h0, l0); split_bf16(v.y, h1, l1);
            split_bf16(v.z, h2, l2); split_bf16(v.w, h3, l3);
            int w = row * GSTRIDE_W + (kc >> 1);
            sAh[w]     = pack_bf16(h0, h1);
            sAh[w + 1] = pack_bf16(h2, h3);
            sAl[w]     = pack_bf16(l0, l1);
            sAl[w + 1] = pack_bf16(l2, l3);
        }

        if (TRANSB) {
#pragma unroll
            for (int p = 0; p < 4; p++) {
                int f4  = tid + 256 * p;
                int row = f4 >> 3;
                int kc  = (f4 & 7) << 2;
                float4 v = make_float4(0.f, 0.f, 0.f, 0.f);
                if (n0 + row < N && k0 + kc < K)
                    v = *(const float4*)(Bm + (size_t)(n0 + row) * K + k0 + kc);
                __nv_bfloat16 h0, h1, h2, h3, l0, l1, l2, l3;
                split_bf16(v.x, h0, l0); split_bf16(v.y, h1, l1);
                split_bf16(v.z, h2, l2); split_bf16(v.w, h3, l3);
                int w = row * GSTRIDE_W + (kc >> 1);
                sBh[w]     = pack_bf16(h0, h1);
                sBh[w + 1] = pack_bf16(h2, h3);
                sBl[w]     = pack_bf16(l0, l1);
                sBl[w + 1] = pack_bf16(l2, l3);
            }
        } else {
            const int n  = tid & 127;
            const int kr = tid >> 7;
            const bool nok = (n0 + n) < N;
            __nv_bfloat16* bh16 = (__nv_bfloat16*)sBh;
            __nv_bfloat16* bl16 = (__nv_bfloat16*)sBl;
#pragma unroll
            for (int p = 0; p < 16; p++) {
                int k = kr + 2 * p;
                float v = 0.f;
                if (nok && (k0 + k) < K)
                    v = Bm[(size_t)(k0 + k) * N + n0 + n];
                __nv_bfloat16 h, l;
                split_bf16(v, h, l);
                bh16[n * (2 * GSTRIDE_W) + k] = h;
                bl16[n * (2 * GSTRIDE_W) + k] = l;
            }
        }

        __syncthreads();

#pragma unroll
        for (int ks = 0; ks < 2; ks++) {
            const int kw = ks * 8;
            uint32_t bh[4][2], bl[4][2];
#pragma unroll
            for (int ni = 0; ni < 4; ni++) {
                int base = (wn * 32 + ni * 8 + g) * GSTRIDE_W + kw + c;
                bh[ni][0] = sBh[base]; bh[ni][1] = sBh[base + 4];
                bl[ni][0] = sBl[base]; bl[ni][1] = sBl[base + 4];
            }
#pragma unroll
            for (int mi = 0; mi < 4; mi++) {
                int base = (wm * 64 + mi * 16 + g) * GSTRIDE_W + kw + c;
                uint32_t ah[4], al[4];
                ah[0] = sAh[base];       ah[1] = sAh[base + 8 * GSTRIDE_W];
                ah[2] = sAh[base + 4];   ah[3] = sAh[base + 4 + 8 * GSTRIDE_W];
                al[0] = sAl[base];       al[1] = sAl[base + 8 * GSTRIDE_W];
                al[2] = sAl[base + 4];   al[3] = sAl[base + 4 + 8 * GSTRIDE_W];
#pragma unroll
                for (int ni = 0; ni < 4; ni++) {
                    mma16816(acc[mi][ni], ah, bh[ni]);
                    mma16816(acc[mi][ni], al, bh[ni]);
                    mma16816(acc[mi][ni], ah, bl[ni]);
                }
            }
        }
    }

#pragma unroll
    for (int mi = 0; mi < 4; mi++) {
#pragma unroll
        for (int ni = 0; ni < 4; ni++) {
            int row = m0 + wm * 64 + mi * 16 + g;
            int col = n0 + wn * 32 + ni * 8 + 2 * c;
            if (col < N) {
                float bx = 0.f, by = 0.f;
                if (bias != nullptr) { bx = bias[col]; by = bias[col + 1]; }
                float2 o0, o1;
                o0.x = acc[mi][ni][0] + bx; o0.y = acc[mi][ni][1] + by;
                o1.x = acc[mi][ni][2] + bx; o1.y = acc[mi][ni][3] + by;
                if (RELU) {
                    o0.x = fmaxf(o0.x, 0.f); o0.y = fmaxf(o0.y, 0.f);
                    o1.x = fmaxf(o1.x, 0.f); o1.y = fmaxf(o1.y, 0.f);
                }
                *(float2*)(C + (size_t)row * N + col) = o0;
                *(float2*)(C + (size_t)(row + 8) * N + col) = o1;
            }
        }
    }
}

// =====================================================================
// mma.sync flash attention, bf16x3 split (QK and PV), 128 q x 64 s tiles.
// 8 warps x 16 q-rows. K padded 200->208 (13 k16 steps). P stays in regs
// (score C-frag == P A-frag layout). SRL consumed via ldmatrix.trans.
//
// smem (bf16x2 words):
//   qh[128][108], ql[128][108]   (216 bf16 row stride; 108%32=12 -> conflict-free)
//   yh[64][108],  yl[64][108]
//   sh[64][68],   sl[64][68]     (136 bf16 stride; 68%32=4 -> conflict-free)
// total 50176 words = 200704 B dynamic smem.
// =====================================================================
#define AT_QH 0
#define AT_QL 13824
#define AT_YH 27648
#define AT_YL 34560
#define AT_SH 41472
#define AT_SL 45824
#define AT_WORDS 50176
#define ATTN_SMEM_BYTES (AT_WORDS * 4)   // 200704

__global__ __launch_bounds__(256) void attn_kernel(
    const float* __restrict__ q,    // [B,S,200]
    const float* __restrict__ y,    // [B,S,200]
    const float* __restrict__ srl,  // [B,S,128]
    float* __restrict__ out)        // [B,S,128]
{
    extern __shared__ uint32_t smw[];
    uint32_t* qh = smw + AT_QH;
    uint32_t* ql = smw + AT_QL;
    uint32_t* yh = smw + AT_YH;
    uint32_t* yl = smw + AT_YL;
    uint32_t* sh = smw + AT_SH;
    uint32_t* sl = smw + AT_SL;

    const uint32_t base_b = smem_u32(smw);
    const int tid  = threadIdx.x;
    const int wid  = tid >> 5;      // 0..7
    const int lane = tid & 31;
    const int g    = lane >> 2;
    const int c    = lane & 3;
    const int bb   = blockIdx.y;
    const int q0   = blockIdx.x * 128;
    const int q0w  = wid * 16;

    const float* qb  = q   + ((size_t)bb * SEQ + q0) * DDIM;
    const float* yb  = y   + (size_t)bb * SEQ * DDIM;
    const float* srb = srl + (size_t)bb * SEQ * VDIM;

    // per-thread ldmatrix base offsets (in words)
    const int qrow_off = (q0w + (lane & 15)) * 108 + (lane >> 4) * 4;
    const int yrow_off = (8 * (lane >> 4) + (lane & 7)) * 108 + ((lane >> 3) & 1) * 4;
    const int srow_off = (((lane >> 3) & 1) * 8 + (lane & 7)) * 68 + (lane >> 4) * 4;
    const uint32_t qh_b = base_b + AT_QH * 4 + qrow_off * 4;
    const uint32_t ql_b = base_b + AT_QL * 4 + qrow_off * 4;
    const uint32_t yh_b = base_b + AT_YH * 4 + yrow_off * 4;
    const uint32_t yl_b = base_b + AT_YL * 4 + yrow_off * 4;
    const uint32_t sh_b = base_b + AT_SH * 4 + srow_off * 4;
    const uint32_t sl_b = base_b + AT_SL * 4 + srow_off * 4;

    // ---- zero k-pad words (k 200..207 -> words 100..103) ----
    for (int idx = tid; idx < 128 * 4; idx += 256) {
        int r = idx >> 2, w = 100 + (idx & 3);
        qh[r * 108 + w] = 0; ql[r * 108 + w] = 0;
        if (r < 64) { yh[r * 108 + w] = 0; yl[r * 108 + w] = 0; }
    }

    // ---- load Q tile once: [128][200] fp32 -> hi/lo bf16 ----
    for (int idx = tid; idx < 128 * 50; idx += 256) {
        int r = idx / 50, c4 = idx % 50;
        float4 v = *(const float4*)(qb + (size_t)r * DDIM + 4 * c4);
        uint32_t h0, l0, h1, l1;
        split_pack2(v.x, v.y, h0, l0);
        split_pack2(v.z, v.w, h1, l1);
        int w = r * 108 + 2 * c4;
        qh[w] = h0; qh[w + 1] = h1;
        ql[w] = l0; ql[w + 1] = l1;
    }

    float m0v = -1e30f, m1v = -1e30f, l0v = 0.f, l1v = 0.f;
    float acc[16][4];
#pragma unroll
    for (int t = 0; t < 16; t++)
#pragma unroll
        for (int r = 0; r < 4; r++) acc[t][r] = 0.f;

    for (int s0 = 0; s0 < SEQ; s0 += 64) {
        __syncthreads();   // previous iteration's reads complete

        // ---- load Y tile [64][200] ----
        for (int idx = tid; idx < 64 * 50; idx += 256) {
            int r = idx / 50, c4 = idx % 50;
            float4 v = *(const float4*)(yb + (size_t)(s0 + r) * DDIM + 4 * c4);
            uint32_t h0, l0, h1, l1;
            split_pack2(v.x, v.y, h0, l0);
            split_pack2(v.z, v.w, h1, l1);
            int w = r * 108 + 2 * c4;
            yh[w] = h0; yh[w + 1] = h1;
            yl[w] = l0; yl[w + 1] = l1;
        }
        // ---- load SRL tile [64][128] (same layout as gmem) ----
        for (int idx = tid; idx < 64 * 32; idx += 256) {
            int r = idx >> 5, v4 = idx & 31;
            float4 v = *(const float4*)(srb + (size_t)(s0 + r) * VDIM + 4 * v4);
            uint32_t h0, l0, h1, l1;
            split_pack2(v.x, v.y, h0, l0);
            split_pack2(v.z, v.w, h1, l1);
            int w = r * 68 + 2 * v4;
            sh[w] = h0; sh[w + 1] = h1;
            sl[w] = l0; sl[w + 1] = l1;
        }
        __syncthreads();

        // ---- QK^T: sc[8 n-tiles][4], 13 k16 steps x 3 splits ----
        float sc[8][4];
#pragma unroll
        for (int t = 0; t < 8; t++)
#pragma unroll
            for (int r = 0; r < 4; r++) sc[t][r] = 0.f;

#pragma unroll
        for (int h = 0; h < 13; h++) {
            uint32_t ah[4], al[4];
            ldmx4(ah, qh_b + h * 32);
            ldmx4(al, ql_b + h * 32);
#pragma unroll
            for (int t2 = 0; t2 < 4; t2++) {
                uint32_t bh[4], bl[4];
                ldmx4(bh, yh_b + (t2 * 1728 + h * 8) * 4);
                ldmx4(bl, yl_b + (t2 * 1728 + h * 8) * 4);
                mma2(sc[2 * t2],     ah, bh[0], bh[1]);
                mma2(sc[2 * t2],     al, bh[0], bh[1]);
                mma2(sc[2 * t2],     ah, bl[0], bl[1]);
                mma2(sc[2 * t2 + 1], ah, bh[2], bh[3]);
                mma2(sc[2 * t2 + 1], al, bh[2], bh[3]);
                mma2(sc[2 * t2 + 1], ah, bl[2], bl[3]);
            }
        }

        // ---- online softmax (rows g, g+8; cols spread over quad lanes) ----
        float mx0 = sc[0][0], mx1 = sc[0][2];
#pragma unroll
        for (int t = 0; t < 8; t++) {
            mx0 = fmaxf(mx0, fmaxf(sc[t][0], sc[t][1]));
            mx1 = fmaxf(mx1, fmaxf(sc[t][2], sc[t][3]));
        }
        mx0 = fmaxf(mx0, __shfl_xor_sync(0xffffffffu, mx0, 1));
        mx0 = fmaxf(mx0, __shfl_xor_sync(0xffffffffu, mx0, 2));
        mx1 = fmaxf(mx1, __shfl_xor_sync(0xffffffffu, mx1, 1));
        mx1 = fmaxf(mx1, __shfl_xor_sync(0xffffffffu, mx1, 2));
        float mn0 = fmaxf(m0v, mx0), mn1 = fmaxf(m1v, mx1);
        float ts0 = 0.f, ts1 = 0.f;
#pragma unroll
        for (int t = 0; t < 8; t++) {
            sc[t][0] = __expf(sc[t][0] - mn0); ts0 += sc[t][0];
            sc[t][1] = __expf(sc[t][1] - mn0); ts0 += sc[t][1];
            sc[t][2] = __expf(sc[t][2] - mn1); ts1 += sc[t][2];
            sc[t][3] = __expf(sc[t][3] - mn1); ts1 += sc[t][3];
        }
        ts0 += __shfl_xor_sync(0xffffffffu, ts0, 1);
        ts0 += __shfl_xor_sync(0xffffffffu, ts0, 2);
        ts1 += __shfl_xor_sync(0xffffffffu, ts1, 1);
        ts1 += __shfl_xor_sync(0xffffffffu, ts1, 2);
        float f0 = __expf(m0v - mn0), f1 = __expf(m1v - mn1);
        l0v = l0v * f0 + ts0; l1v = l1v * f1 + ts1;
        m0v = mn0; m1v = mn1;
#pragma unroll
        for (int t = 0; t < 16; t++) {
            acc[t][0] *= f0; acc[t][1] *= f0;
            acc[t][2] *= f1; acc[t][3] *= f1;
        }

        // ---- PV: P (in regs, split) @ SRL, 4 k16 steps x 16 v-tiles x 3 ----
#pragma unroll
        for (int h = 0; h < 4; h++) {
            uint32_t pah[4], pal[4];
            split_pack2(sc[2 * h][0],     sc[2 * h][1],     pah[0], pal[0]);
            split_pack2(sc[2 * h][2],     sc[2 * h][3],     pah[1], pal[1]);
            split_pack2(sc[2 * h + 1][0], sc[2 * h + 1][1], pah[2], pal[2]);
            split_pack2(sc[2 * h + 1][2], sc[2 * h + 1][3], pah[3], pal[3]);
#pragma unroll
            for (int t2 = 0; t2 < 8; t2++) {
                uint32_t bh[4], bl[4];
                ldmx4t(bh, sh_b + (h * 1088 + t2 * 8) * 4);
                ldmx4t(bl, sl_b + (h * 1088 + t2 * 8) * 4);
                mma2(acc[2 * t2],     pah, bh[0], bh[1]);
                mma2(acc[2 * t2],     pal, bh[0], bh[1]);
                mma2(acc[2 * t2],     pah, bl[0], bl[1]);
                mma2(acc[2 * t2 + 1], pah, bh[2], bh[3]);
                mma2(acc[2 * t2 + 1], pal, bh[2], bh[3]);
                mma2(acc[2 * t2 + 1], pah, bl[2], bl[3]);
            }
        }
    }

    // ---- normalize + store ----
    float inv0 = 1.f / l0v, inv1 = 1.f / l1v;
    int row0 = q0 + q0w + g;
    float* op0 = out + ((size_t)bb * SEQ + row0) * VDIM;
    float* op1 = op0 + 8 * VDIM;
#pragma unroll
    for (int t = 0; t < 16; t++) {
        int col = 8 * t + 2 * c;
        float2 o0, o1;
        o0.x = acc[t][0] * inv0; o0.y = acc[t][1] * inv0;
        o1.x = acc[t][2] * inv1; o1.y = acc[t][3] * inv1;
        *(float2*)(op0 + col) = o0;
        *(float2*)(op1 + col) = o1;
    }
}

// =====================================================================
// launcher
// =====================================================================
extern "C" void kernel_launch(void* const* d_in, const int* in_sizes, int n_in,
                              void* d_out, int out_size)
{
    (void)in_sizes; (void)n_in; (void)out_size;
    const float* mem = (const float*)d_in[0];   // [32,1024,200]
    const float* srl = (const float*)d_in[1];   // [32,1024,128]
    const float* emb = (const float*)d_in[2];   // [32,1024,768]
    const float* W1  = (const float*)d_in[4];   // [768,300]
    const float* b1  = (const float*)d_in[5];
    const float* W2  = (const float*)d_in[6];   // [300,200]
    const float* b2  = (const float*)d_in[7];
    const float* mat = (const float*)d_in[8];   // [200,200]
    const float* Wp  = (const float*)d_in[9];   // [128,128]
    const float* bp  = (const float*)d_in[10];
    float* outp = (float*)d_out;                // [32768,128]

    float *h, *qv, *yv, *att;
    cudaGetSymbolAddress((void**)&h,   g_h);
    cudaGetSymbolAddress((void**)&qv,  g_q);
    cudaGetSymbolAddress((void**)&yv,  g_y);
    cudaGetSymbolAddress((void**)&att, g_att);

    cudaFuncSetAttribute(attn_kernel,
                         cudaFuncAttributeMaxDynamicSharedMemorySize, ATTN_SMEM_BYTES);

    // G1: h = relu(emb @ W1 + b1)   [32768,300]
    gemm_mma<false, true><<<dim3(3, 256), 256>>>(emb, W1, b1, h, MTOT, H1, EMB);
    // G2: q = relu(h @ W2 + b2)     [32768,200]
    gemm_mma<false, true><<<dim3(2, 256), 256>>>(h, W2, b2, qv, MTOT, DDIM, H1);
    // G3: y = mem @ matrix          [32768,200]
    gemm_mma<false, false><<<dim3(2, 256), 256>>>(mem, mat, nullptr, yv, MTOT, DDIM, DDIM);
    // fused attention -> att        [32768,128]
    attn_kernel<<<dim3(SEQ / 128, BATCH), 256, ATTN_SMEM_BYTES>>>(qv, yv, srl, att);
    // G5: out = att @ Wp^T + bp     [32768,128]
    gemm_mma<true, false><<<dim3(1, 256), 256>>>(att, Wp, bp, outp, MTOT, VDIM, VDIM);
}

// round 7
// speedup vs baseline: 1.9701x; 1.1305x over previous
#include <cuda_runtime.h>
#include <cuda_bf16.h>
#include <cstdint>
#include <cstddef>

// Problem constants
#define BATCH 32
#define SEQ   1024
#define VDIM  128
#define EMB   768
#define H1    300
#define DDIM  200
#define MTOT  (BATCH*SEQ)   // 32768

// ---------------- bf16 split helpers ----------------
__device__ __forceinline__ uint32_t pack_bf16(__nv_bfloat16 lo16, __nv_bfloat16 hi16) {
    __nv_bfloat162 t(lo16, hi16);
    return *(uint32_t*)&t;
}
__device__ __forceinline__ void split_bf16(float v, __nv_bfloat16& h, __nv_bfloat16& l) {
    h = __float2bfloat16(v);
    l = __float2bfloat16(v - __bfloat162float(h));
}
__device__ __forceinline__ void split_pack2(float x, float y, uint32_t& hi, uint32_t& lo) {
    __nv_bfloat16 hx, lx, hy, ly;
    split_bf16(x, hx, lx);
    split_bf16(y, hy, ly);
    hi = pack_bf16(hx, hy);
    lo = pack_bf16(lx, ly);
}

// mma.sync m16n8k16 bf16: D += A*B  (row.col)
__device__ __forceinline__ void mma16816(float* d, const uint32_t* a, const uint32_t* b) {
    asm volatile(
        "mma.sync.aligned.m16n8k16.row.col.f32.bf16.bf16.f32 "
        "{%0,%1,%2,%3}, {%4,%5,%6,%7}, {%8,%9}, {%0,%1,%2,%3};"
        : "+f"(d[0]), "+f"(d[1]), "+f"(d[2]), "+f"(d[3])
        : "r"(a[0]), "r"(a[1]), "r"(a[2]), "r"(a[3]), "r"(b[0]), "r"(b[1]));
}
__device__ __forceinline__ void mma2(float* d, const uint32_t* a, uint32_t b0, uint32_t b1) {
    asm volatile(
        "mma.sync.aligned.m16n8k16.row.col.f32.bf16.bf16.f32 "
        "{%0,%1,%2,%3}, {%4,%5,%6,%7}, {%8,%9}, {%0,%1,%2,%3};"
        : "+f"(d[0]), "+f"(d[1]), "+f"(d[2]), "+f"(d[3])
        : "r"(a[0]), "r"(a[1]), "r"(a[2]), "r"(a[3]), "r"(b0), "r"(b1));
}

__device__ __forceinline__ uint32_t smem_u32(const void* p) {
    uint32_t a;
    asm("{ .reg .u64 t; cvta.to.shared.u64 t, %1; cvt.u32.u64 %0, t; }"
        : "=r"(a) : "l"(p));
    return a;
}
__device__ __forceinline__ void ldmx4(uint32_t* r, uint32_t addr) {
    asm volatile("ldmatrix.sync.aligned.m8n8.x4.shared.b16 {%0,%1,%2,%3}, [%4];"
        : "=r"(r[0]), "=r"(r[1]), "=r"(r[2]), "=r"(r[3]) : "r"(addr));
}
__device__ __forceinline__ void ldmx4t(uint32_t* r, uint32_t addr) {
    asm volatile("ldmatrix.sync.aligned.m8n8.x4.trans.shared.b16 {%0,%1,%2,%3}, [%4];"
        : "=r"(r[0]), "=r"(r[1]), "=r"(r[2]), "=r"(r[3]) : "r"(addr));
}

// ---------------- scratch (static device arrays; no allocation) ----------------
__device__ __align__(128) float g_h[(size_t)MTOT * H1];
__device__ __align__(128) float g_q[(size_t)MTOT * DDIM];
__device__ __align__(128) float g_y[(size_t)MTOT * DDIM];
__device__ __align__(128) float g_att[(size_t)MTOT * VDIM];

// =====================================================================
// mma.sync bf16x3-split GEMM, double-buffered.
//   TRANSB=false: B is [K,N] row-major;  TRANSB=true: B is [N,K] (C=A@B^T)
// CTA 128x128, K-chunk 32 fp32. 8 warps (2m x 4n), warp tile 64x32.
// SMEM: 2 stages x (Ah|Al|Bh|Bl)[128][20 words] = 81920 B dynamic.
// Loop: LDG chunk c+1 -> regs; mma chunk c (stage s); convert regs -> stage 1-s;
// one __syncthreads per chunk (write-stage != read-stage).
// =====================================================================
#define GSTRIDE_W 20
#define GSTAGE_W  (4 * 128 * GSTRIDE_W)       // words per stage (10240)
#define GEMM_SMEM_BYTES (2 * GSTAGE_W * 4)    // 81920

template<bool TRANSB, bool RELU>
__global__ __launch_bounds__(256) void gemm_mma(
    const float* __restrict__ A, const float* __restrict__ Bm,
    const float* __restrict__ bias, float* __restrict__ C,
    int M, int N, int K)
{
    extern __shared__ uint32_t smw[];

    const int tid  = threadIdx.x;
    const int wid  = tid >> 5;
    const int lane = tid & 31;
    const int g    = lane >> 2;
    const int c    = lane & 3;
    const int wm   = wid & 1;
    const int wn   = wid >> 1;
    const int m0 = blockIdx.y * 128;
    const int n0 = blockIdx.x * 128;

    float acc[4][4][4];
#pragma unroll
    for (int mi = 0; mi < 4; mi++)
#pragma unroll
        for (int ni = 0; ni < 4; ni++)
#pragma unroll
            for (int r = 0; r < 4; r++) acc[mi][ni][r] = 0.f;

    float4 av[4];           // staged A chunk (16 floats)
    float4 bv[4];           // staged B chunk (TRANSB path)
    float  bs[16];          // staged B chunk (non-trans path)

    // ---------- loaders ----------
    auto loadA = [&](int k0) {
#pragma unroll
        for (int p = 0; p < 4; p++) {
            int f4  = tid + 256 * p;
            int row = f4 >> 3;
            int kc  = (f4 & 7) << 2;
            av[p] = make_float4(0.f, 0.f, 0.f, 0.f);
            if (k0 + kc < K)
                av[p] = *(const float4*)(A + (size_t)(m0 + row) * K + k0 + kc);
        }
    };
    auto loadB = [&](int k0) {
        if (TRANSB) {
#pragma unroll
            for (int p = 0; p < 4; p++) {
                int f4  = tid + 256 * p;
                int row = f4 >> 3;
                int kc  = (f4 & 7) << 2;
                bv[p] = make_float4(0.f, 0.f, 0.f, 0.f);
                if (n0 + row < N && k0 + kc < K)
                    bv[p] = *(const float4*)(Bm + (size_t)(n0 + row) * K + k0 + kc);
            }
        } else {
            const int n  = tid & 127;
            const int kr = tid >> 7;
            const bool nok = (n0 + n) < N;
#pragma unroll
            for (int p = 0; p < 16; p++) {
                int k = kr + 2 * p;
                bs[p] = 0.f;
                if (nok && (k0 + k) < K)
                    bs[p] = Bm[(size_t)(k0 + k) * N + n0 + n];
            }
        }
    };
    // ---------- convert + store to a stage ----------
    auto storeStage = [&](int st) {
        uint32_t* sAh = smw + st * GSTAGE_W;
        uint32_t* sAl = sAh + 2560;
        uint32_t* sBh = sAh + 5120;
        uint32_t* sBl = sAh + 7680;
#pragma unroll
        for (int p = 0; p < 4; p++) {
            int f4  = tid + 256 * p;
            int row = f4 >> 3;
            int kc  = (f4 & 7) << 2;
            uint32_t h0, l0, h1, l1;
            split_pack2(av[p].x, av[p].y, h0, l0);
            split_pack2(av[p].z, av[p].w, h1, l1);
            int w = row * GSTRIDE_W + (kc >> 1);
            sAh[w] = h0; sAh[w + 1] = h1;
            sAl[w] = l0; sAl[w + 1] = l1;
        }
        if (TRANSB) {
#pragma unroll
            for (int p = 0; p < 4; p++) {
                int f4  = tid + 256 * p;
                int row = f4 >> 3;
                int kc  = (f4 & 7) << 2;
                uint32_t h0, l0, h1, l1;
                split_pack2(bv[p].x, bv[p].y, h0, l0);
                split_pack2(bv[p].z, bv[p].w, h1, l1);
                int w = row * GSTRIDE_W + (kc >> 1);
                sBh[w] = h0; sBh[w + 1] = h1;
                sBl[w] = l0; sBl[w + 1] = l1;
            }
        } else {
            const int n  = tid & 127;
            const int kr = tid >> 7;
            __nv_bfloat16* bh16 = (__nv_bfloat16*)sBh;
            __nv_bfloat16* bl16 = (__nv_bfloat16*)sBl;
#pragma unroll
            for (int p = 0; p < 16; p++) {
                int k = kr + 2 * p;
                __nv_bfloat16 h, l;
                split_bf16(bs[p], h, l);
                bh16[n * (2 * GSTRIDE_W) + k] = h;
                bl16[n * (2 * GSTRIDE_W) + k] = l;
            }
        }
    };
    // ---------- mma on a stage ----------
    auto compute = [&](int st) {
        uint32_t* sAh = smw + st * GSTAGE_W;
        uint32_t* sAl = sAh + 2560;
        uint32_t* sBh = sAh + 5120;
        uint32_t* sBl = sAh + 7680;
#pragma unroll
        for (int ks = 0; ks < 2; ks++) {
            const int kw = ks * 8;
            uint32_t bh[4][2], bl[4][2];
#pragma unroll
            for (int ni = 0; ni < 4; ni++) {
                int base = (wn * 32 + ni * 8 + g) * GSTRIDE_W + kw + c;
                bh[ni][0] = sBh[base]; bh[ni][1] = sBh[base + 4];
                bl[ni][0] = sBl[base]; bl[ni][1] = sBl[base + 4];
            }
#pragma unroll
            for (int mi = 0; mi < 4; mi++) {
                int base = (wm * 64 + mi * 16 + g) * GSTRIDE_W + kw + c;
                uint32_t ah[4], al[4];
                ah[0] = sAh[base];       ah[1] = sAh[base + 8 * GSTRIDE_W];
                ah[2] = sAh[base + 4];   ah[3] = sAh[base + 4 + 8 * GSTRIDE_W];
                al[0] = sAl[base];       al[1] = sAl[base + 8 * GSTRIDE_W];
                al[2] = sAl[base + 4];   al[3] = sAl[base + 4 + 8 * GSTRIDE_W];
#pragma unroll
                for (int ni = 0; ni < 4; ni++) {
                    mma16816(acc[mi][ni], ah, bh[ni]);
                    mma16816(acc[mi][ni], al, bh[ni]);
                    mma16816(acc[mi][ni], ah, bl[ni]);
                }
            }
        }
    };

    const int nch = (K + 31) >> 5;

    // prologue: fill stage 0
    loadA(0); loadB(0);
    storeStage(0);
    __syncthreads();

    for (int ck = 0; ck < nch; ck++) {
        const int st = ck & 1;
        if (ck + 1 < nch) { loadA((ck + 1) << 5); loadB((ck + 1) << 5); }
        compute(st);
        if (ck + 1 < nch) storeStage(1 - st);
        __syncthreads();
    }

    // ---- epilogue ----
#pragma unroll
    for (int mi = 0; mi < 4; mi++) {
#pragma unroll
        for (int ni = 0; ni < 4; ni++) {
            int row = m0 + wm * 64 + mi * 16 + g;
            int col = n0 + wn * 32 + ni * 8 + 2 * c;
            if (col < N) {
                float bx = 0.f, by = 0.f;
                if (bias != nullptr) { bx = bias[col]; by = bias[col + 1]; }
                float2 o0, o1;
                o0.x = acc[mi][ni][0] + bx; o0.y = acc[mi][ni][1] + by;
                o1.x = acc[mi][ni][2] + bx; o1.y = acc[mi][ni][3] + by;
                if (RELU) {
                    o0.x = fmaxf(o0.x, 0.f); o0.y = fmaxf(o0.y, 0.f);
                    o1.x = fmaxf(o1.x, 0.f); o1.y = fmaxf(o1.y, 0.f);
                }
                *(float2*)(C + (size_t)row * N + col) = o0;
                *(float2*)(C + (size_t)(row + 8) * N + col) = o1;
            }
        }
    }
}

// =====================================================================
// mma.sync flash attention, bf16x3 split (unchanged from round 6, passing)
// =====================================================================
#define AT_QH 0
#define AT_QL 13824
#define AT_YH 27648
#define AT_YL 34560
#define AT_SH 41472
#define AT_SL 45824
#define AT_WORDS 50176
#define ATTN_SMEM_BYTES (AT_WORDS * 4)   // 200704

__global__ __launch_bounds__(256) void attn_kernel(
    const float* __restrict__ q,    // [B,S,200]
    const float* __restrict__ y,    // [B,S,200]
    const float* __restrict__ srl,  // [B,S,128]
    float* __restrict__ out)        // [B,S,128]
{
    extern __shared__ uint32_t smw[];
    uint32_t* qh = smw + AT_QH;
    uint32_t* ql = smw + AT_QL;
    uint32_t* yh = smw + AT_YH;
    uint32_t* yl = smw + AT_YL;
    uint32_t* sh = smw + AT_SH;
    uint32_t* sl = smw + AT_SL;

    const uint32_t base_b = smem_u32(smw);
    const int tid  = threadIdx.x;
    const int wid  = tid >> 5;
    const int lane = tid & 31;
    const int g    = lane >> 2;
    const int c    = lane & 3;
    const int bb   = blockIdx.y;
    const int q0   = blockIdx.x * 128;
    const int q0w  = wid * 16;

    const float* qb  = q   + ((size_t)bb * SEQ + q0) * DDIM;
    const float* yb  = y   + (size_t)bb * SEQ * DDIM;
    const float* srb = srl + (size_t)bb * SEQ * VDIM;

    const int qrow_off = (q0w + (lane & 15)) * 108 + (lane >> 4) * 4;
    const int yrow_off = (8 * (lane >> 4) + (lane & 7)) * 108 + ((lane >> 3) & 1) * 4;
    const int srow_off = (((lane >> 3) & 1) * 8 + (lane & 7)) * 68 + (lane >> 4) * 4;
    const uint32_t qh_b = base_b + AT_QH * 4 + qrow_off * 4;
    const uint32_t ql_b = base_b + AT_QL * 4 + qrow_off * 4;
    const uint32_t yh_b = base_b + AT_YH * 4 + yrow_off * 4;
    const uint32_t yl_b = base_b + AT_YL * 4 + yrow_off * 4;
    const uint32_t sh_b = base_b + AT_SH * 4 + srow_off * 4;
    const uint32_t sl_b = base_b + AT_SL * 4 + srow_off * 4;

    for (int idx = tid; idx < 128 * 4; idx += 256) {
        int r = idx >> 2, w = 100 + (idx & 3);
        qh[r * 108 + w] = 0; ql[r * 108 + w] = 0;
        if (r < 64) { yh[r * 108 + w] = 0; yl[r * 108 + w] = 0; }
    }

    for (int idx = tid; idx < 128 * 50; idx += 256) {
        int r = idx / 50, c4 = idx % 50;
        float4 v = *(const float4*)(qb + (size_t)r * DDIM + 4 * c4);
        uint32_t h0, l0, h1, l1;
        split_pack2(v.x, v.y, h0, l0);
        split_pack2(v.z, v.w, h1, l1);
        int w = r * 108 + 2 * c4;
        qh[w] = h0; qh[w + 1] = h1;
        ql[w] = l0; ql[w + 1] = l1;
    }

    float m0v = -1e30f, m1v = -1e30f, l0v = 0.f, l1v = 0.f;
    float acc[16][4];
#pragma unroll
    for (int t = 0; t < 16; t++)
#pragma unroll
        for (int r = 0; r < 4; r++) acc[t][r] = 0.f;

    for (int s0 = 0; s0 < SEQ; s0 += 64) {
        __syncthreads();

        for (int idx = tid; idx < 64 * 50; idx += 256) {
            int r = idx / 50, c4 = idx % 50;
            float4 v = *(const float4*)(yb + (size_t)(s0 + r) * DDIM + 4 * c4);
            uint32_t h0, l0, h1, l1;
            split_pack2(v.x, v.y, h0, l0);
            split_pack2(v.z, v.w, h1, l1);
            int w = r * 108 + 2 * c4;
            yh[w] = h0; yh[w + 1] = h1;
            yl[w] = l0; yl[w + 1] = l1;
        }
        for (int idx = tid; idx < 64 * 32; idx += 256) {
            int r = idx >> 5, v4 = idx & 31;
            float4 v = *(const float4*)(srb + (size_t)(s0 + r) * VDIM + 4 * v4);
            uint32_t h0, l0, h1, l1;
            split_pack2(v.x, v.y, h0, l0);
            split_pack2(v.z, v.w, h1, l1);
            int w = r * 68 + 2 * v4;
            sh[w] = h0; sh[w + 1] = h1;
            sl[w] = l0; sl[w + 1] = l1;
        }
        __syncthreads();

        float sc[8][4];
#pragma unroll
        for (int t = 0; t < 8; t++)
#pragma unroll
            for (int r = 0; r < 4; r++) sc[t][r] = 0.f;

#pragma unroll
        for (int h = 0; h < 13; h++) {
            uint32_t ah[4], al[4];
            ldmx4(ah, qh_b + h * 32);
            ldmx4(al, ql_b + h * 32);
#pragma unroll
            for (int t2 = 0; t2 < 4; t2++) {
                uint32_t bh[4], bl[4];
                ldmx4(bh, yh_b + (t2 * 1728 + h * 8) * 4);
                ldmx4(bl, yl_b + (t2 * 1728 + h * 8) * 4);
                mma2(sc[2 * t2],     ah, bh[0], bh[1]);
                mma2(sc[2 * t2],     al, bh[0], bh[1]);
                mma2(sc[2 * t2],     ah, bl[0], bl[1]);
                mma2(sc[2 * t2 + 1], ah, bh[2], bh[3]);
                mma2(sc[2 * t2 + 1], al, bh[2], bh[3]);
                mma2(sc[2 * t2 + 1], ah, bl[2], bl[3]);
            }
        }

        float mx0 = sc[0][0], mx1 = sc[0][2];
#pragma unroll
        for (int t = 0; t < 8; t++) {
            mx0 = fmaxf(mx0, fmaxf(sc[t][0], sc[t][1]));
            mx1 = fmaxf(mx1, fmaxf(sc[t][2], sc[t][3]));
        }
        mx0 = fmaxf(mx0, __shfl_xor_sync(0xffffffffu, mx0, 1));
        mx0 = fmaxf(mx0, __shfl_xor_sync(0xffffffffu, mx0, 2));
        mx1 = fmaxf(mx1, __shfl_xor_sync(0xffffffffu, mx1, 1));
        mx1 = fmaxf(mx1, __shfl_xor_sync(0xffffffffu, mx1, 2));
        float mn0 = fmaxf(m0v, mx0), mn1 = fmaxf(m1v, mx1);
        float ts0 = 0.f, ts1 = 0.f;
#pragma unroll
        for (int t = 0; t < 8; t++) {
            sc[t][0] = __expf(sc[t][0] - mn0); ts0 += sc[t][0];
            sc[t][1] = __expf(sc[t][1] - mn0); ts0 += sc[t][1];
            sc[t][2] = __expf(sc[t][2] - mn1); ts1 += sc[t][2];
            sc[t][3] = __expf(sc[t][3] - mn1); ts1 += sc[t][3];
        }
        ts0 += __shfl_xor_sync(0xffffffffu, ts0, 1);
        ts0 += __shfl_xor_sync(0xffffffffu, ts0, 2);
        ts1 += __shfl_xor_sync(0xffffffffu, ts1, 1);
        ts1 += __shfl_xor_sync(0xffffffffu, ts1, 2);
        float f0 = __expf(m0v - mn0), f1 = __expf(m1v - mn1);
        l0v = l0v * f0 + ts0; l1v = l1v * f1 + ts1;
        m0v = mn0; m1v = mn1;
#pragma unroll
        for (int t = 0; t < 16; t++) {
            acc[t][0] *= f0; acc[t][1] *= f0;
            acc[t][2] *= f1; acc[t][3] *= f1;
        }

#pragma unroll
        for (int h = 0; h < 4; h++) {
            uint32_t pah[4], pal[4];
            split_pack2(sc[2 * h][0],     sc[2 * h][1],     pah[0], pal[0]);
            split_pack2(sc[2 * h][2],     sc[2 * h][3],     pah[1], pal[1]);
            split_pack2(sc[2 * h + 1][0], sc[2 * h + 1][1], pah[2], pal[2]);
            split_pack2(sc[2 * h + 1][2], sc[2 * h + 1][3], pah[3], pal[3]);
#pragma unroll
            for (int t2 = 0; t2 < 8; t2++) {
                uint32_t bh[4], bl[4];
                ldmx4t(bh, sh_b + (h * 1088 + t2 * 8) * 4);
                ldmx4t(bl, sl_b + (h * 1088 + t2 * 8) * 4);
                mma2(acc[2 * t2],     pah, bh[0], bh[1]);
                mma2(acc[2 * t2],     pal, bh[0], bh[1]);
                mma2(acc[2 * t2],     pah, bl[0], bl[1]);
                mma2(acc[2 * t2 + 1], pah, bh[2], bh[3]);
                mma2(acc[2 * t2 + 1], pal, bh[2], bh[3]);
                mma2(acc[2 * t2 + 1], pah, bl[2], bl[3]);
            }
        }
    }

    float inv0 = 1.f / l0v, inv1 = 1.f / l1v;
    int row0 = q0 + q0w + g;
    float* op0 = out + ((size_t)bb * SEQ + row0) * VDIM;
    float* op1 = op0 + 8 * VDIM;
#pragma unroll
    for (int t = 0; t < 16; t++) {
        int col = 8 * t + 2 * c;
        float2 o0, o1;
        o0.x = acc[t][0] * inv0; o0.y = acc[t][1] * inv0;
        o1.x = acc[t][2] * inv1; o1.y = acc[t][3] * inv1;
        *(float2*)(op0 + col) = o0;
        *(float2*)(op1 + col) = o1;
    }
}

// =====================================================================
// launcher
// =====================================================================
extern "C" void kernel_launch(void* const* d_in, const int* in_sizes, int n_in,
                              void* d_out, int out_size)
{
    (void)in_sizes; (void)n_in; (void)out_size;
    const float* mem = (const float*)d_in[0];   // [32,1024,200]
    const float* srl = (const float*)d_in[1];   // [32,1024,128]
    const float* emb = (const float*)d_in[2];   // [32,1024,768]
    const float* W1  = (const float*)d_in[4];   // [768,300]
    const float* b1  = (const float*)d_in[5];
    const float* W2  = (const float*)d_in[6];   // [300,200]
    const float* b2  = (const float*)d_in[7];
    const float* mat = (const float*)d_in[8];   // [200,200]
    const float* Wp  = (const float*)d_in[9];   // [128,128]
    const float* bp  = (const float*)d_in[10];
    float* outp = (float*)d_out;                // [32768,128]

    float *h, *qv, *yv, *att;
    cudaGetSymbolAddress((void**)&h,   g_h);
    cudaGetSymbolAddress((void**)&qv,  g_q);
    cudaGetSymbolAddress((void**)&yv,  g_y);
    cudaGetSymbolAddress((void**)&att, g_att);

    cudaFuncSetAttribute(attn_kernel,
                         cudaFuncAttributeMaxDynamicSharedMemorySize, ATTN_SMEM_BYTES);
    cudaFuncSetAttribute(gemm_mma<false, true>,
                         cudaFuncAttributeMaxDynamicSharedMemorySize, GEMM_SMEM_BYTES);
    cudaFuncSetAttribute(gemm_mma<false, false>,
                         cudaFuncAttributeMaxDynamicSharedMemorySize, GEMM_SMEM_BYTES);
    cudaFuncSetAttribute(gemm_mma<true, false>,
                         cudaFuncAttributeMaxDynamicSharedMemorySize, GEMM_SMEM_BYTES);

    // G1: h = relu(emb @ W1 + b1)   [32768,300]
    gemm_mma<false, true><<<dim3(3, 256), 256, GEMM_SMEM_BYTES>>>(emb, W1, b1, h, MTOT, H1, EMB);
    // G2: q = relu(h @ W2 + b2)     [32768,200]
    gemm_mma<false, true><<<dim3(2, 256), 256, GEMM_SMEM_BYTES>>>(h, W2, b2, qv, MTOT, DDIM, H1);
    // G3: y = mem @ matrix          [32768,200]
    gemm_mma<false, false><<<dim3(2, 256), 256, GEMM_SMEM_BYTES>>>(mem, mat, nullptr, yv, MTOT, DDIM, DDIM);
    // fused attention -> att        [32768,128]
    attn_kernel<<<dim3(SEQ / 128, BATCH), 256, ATTN_SMEM_BYTES>>>(qv, yv, srl, att);
    // G5: out = att @ Wp^T + bp     [32768,128]
    gemm_mma<true, false><<<dim3(1, 256), 256, GEMM_SMEM_BYTES>>>(att, Wp, bp, outp, MTOT, VDIM, VDIM);
}

// round 9
// speedup vs baseline: 2.2026x; 1.1180x over previous
#include <cuda_runtime.h>
#include <cuda_bf16.h>
#include <cstdint>
#include <cstddef>

// Problem constants
#define BATCH 32
#define SEQ   1024
#define VDIM  128
#define EMB   768
#define H1    300
#define DDIM  200
#define MTOT  (BATCH*SEQ)   // 32768

// padded dims
#define HP    320   // h cols (G1 store / G2 K)
#define QP    208   // q,y cols (G2/G3 store / attn K)
#define MEMP  224   // mem cols (G3 K)
#define W1NP  384
#define W2NP  256
#define MATNP 256

typedef __nv_bfloat16 bf16;

// ---------------- helpers ----------------
__device__ __forceinline__ uint32_t pack_bf16(bf16 lo16, bf16 hi16) {
    __nv_bfloat162 t(lo16, hi16);
    return *(uint32_t*)&t;
}
__device__ __forceinline__ void split_bf16(float v, bf16& h, bf16& l) {
    h = __float2bfloat16(v);
    l = __float2bfloat16(v - __bfloat162float(h));
}
__device__ __forceinline__ void split_pack2(float x, float y, uint32_t& hi, uint32_t& lo) {
    bf16 hx, lx, hy, ly;
    split_bf16(x, hx, lx);
    split_bf16(y, hy, ly);
    hi = pack_bf16(hx, hy);
    lo = pack_bf16(lx, ly);
}
__device__ __forceinline__ void mma16816(float* d, const uint32_t* a, const uint32_t* b) {
    asm volatile(
        "mma.sync.aligned.m16n8k16.row.col.f32.bf16.bf16.f32 "
        "{%0,%1,%2,%3}, {%4,%5,%6,%7}, {%8,%9}, {%0,%1,%2,%3};"
        : "+f"(d[0]), "+f"(d[1]), "+f"(d[2]), "+f"(d[3])
        : "r"(a[0]), "r"(a[1]), "r"(a[2]), "r"(a[3]), "r"(b[0]), "r"(b[1]));
}
__device__ __forceinline__ void mma2(float* d, const uint32_t* a, uint32_t b0, uint32_t b1) {
    asm volatile(
        "mma.sync.aligned.m16n8k16.row.col.f32.bf16.bf16.f32 "
        "{%0,%1,%2,%3}, {%4,%5,%6,%7}, {%8,%9}, {%0,%1,%2,%3};"
        : "+f"(d[0]), "+f"(d[1]), "+f"(d[2]), "+f"(d[3])
        : "r"(a[0]), "r"(a[1]), "r"(a[2]), "r"(a[3]), "r"(b0), "r"(b1));
}
__device__ __forceinline__ uint32_t smem_u32(const void* p) {
    uint32_t a;
    asm("{ .reg .u64 t; cvta.to.shared.u64 t, %1; cvt.u32.u64 %0, t; }"
        : "=r"(a) : "l"(p));
    return a;
}
__device__ __forceinline__ void ldmx4(uint32_t* r, uint32_t addr) {
    asm volatile("ldmatrix.sync.aligned.m8n8.x4.shared.b16 {%0,%1,%2,%3}, [%4];"
        : "=r"(r[0]), "=r"(r[1]), "=r"(r[2]), "=r"(r[3]) : "r"(addr));
}
__device__ __forceinline__ void ldmx4t(uint32_t* r, uint32_t addr) {
    asm volatile("ldmatrix.sync.aligned.m8n8.x4.trans.shared.b16 {%0,%1,%2,%3}, [%4];"
        : "=r"(r[0]), "=r"(r[1]), "=r"(r[2]), "=r"(r[3]) : "r"(addr));
}
__device__ __forceinline__ void cpa16(uint32_t dst, const void* src) {
    asm volatile("cp.async.cg.shared.global [%0], [%1], 16;" :: "r"(dst), "l"(src));
}
#define CP_COMMIT() asm volatile("cp.async.commit_group;" ::: "memory")
#define CP_WAIT(n)  asm volatile("cp.async.wait_group %0;" :: "n"(n) : "memory")

// ---------------- static scratch (bf16 hi/lo pairs) ----------------
__device__ __align__(128) bf16 g_embh[(size_t)MTOT * EMB],  g_embl[(size_t)MTOT * EMB];
__device__ __align__(128) bf16 g_memh[(size_t)MTOT * MEMP], g_meml[(size_t)MTOT * MEMP];
__device__ __align__(128) bf16 g_srlh[(size_t)MTOT * VDIM], g_srll[(size_t)MTOT * VDIM];
__device__ __align__(128) bf16 g_hh[(size_t)MTOT * HP],     g_hl[(size_t)MTOT * HP];
__device__ __align__(128) bf16 g_qh[(size_t)MTOT * QP],     g_ql[(size_t)MTOT * QP];
__device__ __align__(128) bf16 g_yh[(size_t)MTOT * QP],     g_yl[(size_t)MTOT * QP];
__device__ __align__(128) bf16 g_ath[(size_t)MTOT * VDIM],  g_atl[(size_t)MTOT * VDIM];
__device__ __align__(128) bf16 g_w1th[W1NP * EMB],  g_w1tl[W1NP * EMB];
__device__ __align__(128) bf16 g_w2th[W2NP * HP],   g_w2tl[W2NP * HP];
__device__ __align__(128) bf16 g_math[MATNP * MEMP], g_matl[MATNP * MEMP];
__device__ __align__(128) bf16 g_wph[VDIM * VDIM],  g_wpl[VDIM * VDIM];
__device__ __align__(128) float g_b1p[HP];
__device__ __align__(128) float g_b2p[QP];

// ---------------- prep kernels ----------------
// split fp32 [R][C] -> bf16 hi/lo [R][CP] (zero-padded cols), 2 cols/thread
__global__ void split_pad2(const float* __restrict__ in, bf16* __restrict__ oh,
                           bf16* __restrict__ ol, long long n2, int C, int CP)
{
    long long i2 = (long long)blockIdx.x * blockDim.x + threadIdx.x;
    if (i2 >= n2) return;
    int cp2 = CP >> 1;
    long long r = i2 / cp2;
    int c2 = (int)(i2 - r * cp2) * 2;
    float x = 0.f, y = 0.f;
    if (c2 + 1 < C) {
        float2 v = *(const float2*)(in + r * C + c2);
        x = v.x; y = v.y;
    } else if (c2 < C) {
        x = in[r * C + c2];
    }
    uint32_t h, l;
    split_pack2(x, y, h, l);
    ((uint32_t*)oh)[(r * CP + c2) >> 1] = h;
    ((uint32_t*)ol)[(r * CP + c2) >> 1] = l;
}

// transpose fp32 [K][N] -> bf16 hi/lo [NP][KP] (zero-padded)
__global__ void tsplit(const float* __restrict__ in, bf16* __restrict__ oh,
                       bf16* __restrict__ ol, int K, int N, int KP, int NP)
{
    int i = blockIdx.x * blockDim.x + threadIdx.x;
    if (i >= NP * KP) return;
    int n = i / KP, k = i - n * KP;
    float v = (n < N && k < K) ? in[(size_t)k * N + n] : 0.f;
    bf16 h, l;
    split_bf16(v, h, l);
    oh[i] = h; ol[i] = l;
}

__global__ void padbias(const float* __restrict__ b, float* __restrict__ bp, int N, int NP)
{
    int i = blockIdx.x * blockDim.x + threadIdx.x;
    if (i < NP) bp[i] = (i < N) ? b[i] : 0.f;
}

// =====================================================================
// bf16 pre-split GEMM: C = act(A @ B^T + bias)
// A: hi/lo [M][K] bf16 (K = padded, mult of 32). B: hi/lo [NP][K].
// CTA 128x128, K-chunk 32; cp.async 2-stage pipeline; 8 warps (2m x 4n).
// SPLITOUT: write Ch/Cl bf16 at stride Ns (cols < Ns); else fp32 C stride Ns.
// =====================================================================
#define GSTRIDE_W 20
#define GSTAGE_W  (4 * 128 * GSTRIDE_W)       // 10240 words / stage
#define GEMM_SMEM_BYTES (2 * GSTAGE_W * 4)    // 81920

template<bool RELU, bool SPLITOUT>
__global__ __launch_bounds__(256) void gemm_bf16(
    const bf16* __restrict__ Ah, const bf16* __restrict__ Al,
    const bf16* __restrict__ Bh, const bf16* __restrict__ Bl,
    const float* __restrict__ bias,
    float* __restrict__ C, bf16* __restrict__ Ch, bf16* __restrict__ Cl,
    int Ns, int K)
{
    extern __shared__ uint32_t smw[];
    const uint32_t base_b = smem_u32(smw);

    const int tid  = threadIdx.x;
    const int wid  = tid >> 5;
    const int lane = tid & 31;
    const int g    = lane >> 2;
    const int c    = lane & 3;
    const int wm   = wid & 1;
    const int wn   = wid >> 1;
    const int m0 = blockIdx.y * 128;
    const int n0 = blockIdx.x * 128;

    float acc[4][4][4];
#pragma unroll
    for (int mi = 0; mi < 4; mi++)
#pragma unroll
        for (int ni = 0; ni < 4; ni++)
#pragma unroll
            for (int r = 0; r < 4; r++) acc[mi][ni][r] = 0.f;

    auto loadChunk = [&](int ck, int st) {
        const int k0 = ck << 5;
        const uint32_t stb = base_b + (st ? GSTAGE_W * 4 : 0);
#pragma unroll
        for (int j = 0; j < 8; j++) {
            int idx = tid + 256 * j;
            int which = idx >> 9;          // 0=Ah 1=Al 2=Bh 3=Bl
            int row = (idx >> 2) & 127;
            int part = idx & 3;
            const bf16* base = (which == 0) ? Ah : (which == 1) ? Al
                             : (which == 2) ? Bh : Bl;
            size_t grow = (which < 2) ? (size_t)(m0 + row) * K
                                      : (size_t)(n0 + row) * K;
            uint32_t dst = stb + (which * 2560 + row * GSTRIDE_W + part * 4) * 4;
            cpa16(dst, base + grow + k0 + part * 8);
        }
    };

    auto compute = [&](int st) {
        uint32_t* sAh = smw + st * GSTAGE_W;
        uint32_t* sAl = sAh + 2560;
        uint32_t* sBh = sAh + 5120;
        uint32_t* sBl = sAh + 7680;
#pragma unroll
        for (int ks = 0; ks < 2; ks++) {
            const int kw = ks * 8;
            uint32_t bh[4][2], bl[4][2];
#pragma unroll
            for (int ni = 0; ni < 4; ni++) {
                int base = (wn * 32 + ni * 8 + g) * GSTRIDE_W + kw + c;
                bh[ni][0] = sBh[base]; bh[ni][1] = sBh[base + 4];
                bl[ni][0] = sBl[base]; bl[ni][1] = sBl[base + 4];
            }
#pragma unroll
            for (int mi = 0; mi < 4; mi++) {
                int base = (wm * 64 + mi * 16 + g) * GSTRIDE_W + kw + c;
                uint32_t ah[4], al[4];
                ah[0] = sAh[base];       ah[1] = sAh[base + 8 * GSTRIDE_W];
                ah[2] = sAh[base + 4];   ah[3] = sAh[base + 4 + 8 * GSTRIDE_W];
                al[0] = sAl[base];       al[1] = sAl[base + 8 * GSTRIDE_W];
                al[2] = sAl[base + 4];   al[3] = sAl[base + 4 + 8 * GSTRIDE_W];
#pragma unroll
                for (int ni = 0; ni < 4; ni++) {
                    mma16816(acc[mi][ni], ah, bh[ni]);
                    mma16816(acc[mi][ni], al, bh[ni]);
                    mma16816(acc[mi][ni], ah, bl[ni]);
                }
            }
        }
    };

    const int nch = K >> 5;   // K always multiple of 32

    loadChunk(0, 0);
    CP_COMMIT();
    if (nch > 1) loadChunk(1, 1);
    CP_COMMIT();

    for (int ck = 0; ck < nch; ck++) {
        CP_WAIT(1);
        __syncthreads();
        compute(ck & 1);
        __syncthreads();
        if (ck + 2 < nch) loadChunk(ck + 2, ck & 1);
        CP_COMMIT();
    }

    // ---- epilogue ----
#pragma unroll
    for (int mi = 0; mi < 4; mi++) {
#pragma unroll
        for (int ni = 0; ni < 4; ni++) {
            int row = m0 + wm * 64 + mi * 16 + g;
            int col = n0 + wn * 32 + ni * 8 + 2 * c;
            if (col < Ns) {
                float bx = 0.f, by = 0.f;
                if (bias != nullptr) { bx = bias[col]; by = bias[col + 1]; }
                float2 o0, o1;
                o0.x = acc[mi][ni][0] + bx; o0.y = acc[mi][ni][1] + by;
                o1.x = acc[mi][ni][2] + bx; o1.y = acc[mi][ni][3] + by;
                if (RELU) {
                    o0.x = fmaxf(o0.x, 0.f); o0.y = fmaxf(o0.y, 0.f);
                    o1.x = fmaxf(o1.x, 0.f); o1.y = fmaxf(o1.y, 0.f);
                }
                if (SPLITOUT) {
                    uint32_t h0, l0, h1, l1;
                    split_pack2(o0.x, o0.y, h0, l0);
                    split_pack2(o1.x, o1.y, h1, l1);
                    size_t w0 = ((size_t)row * Ns + col) >> 1;
                    size_t w1 = ((size_t)(row + 8) * Ns + col) >> 1;
                    ((uint32_t*)Ch)[w0] = h0; ((uint32_t*)Cl)[w0] = l0;
                    ((uint32_t*)Ch)[w1] = h1; ((uint32_t*)Cl)[w1] = l1;
                } else {
                    *(float2*)(C + (size_t)row * Ns + col) = o0;
                    *(float2*)(C + (size_t)(row + 8) * Ns + col) = o1;
                }
            }
        }
    }
}

// =====================================================================
// mma.sync flash attention on pre-split bf16 inputs (cp.async loads).
// 128 q x 64 s tiles, 8 warps x 16 q-rows. K = 208 (13 k16 steps).
// Outputs att pre-split bf16 (hi/lo) for G5.
// smem words: qh[128][108] ql[128][108] yh[64][108] yl[64][108]
//             sh[64][68] sl[64][68]  = 50176 words (200704 B)
// =====================================================================
#define AT_QH 0
#define AT_QL 13824
#define AT_YH 27648
#define AT_YL 34560
#define AT_SH 41472
#define AT_SL 45824
#define AT_WORDS 50176
#define ATTN_SMEM_BYTES (AT_WORDS * 4)

__global__ __launch_bounds__(256) void attn_kernel(
    const bf16* __restrict__ qh_g, const bf16* __restrict__ ql_g,   // [B*S][208]
    const bf16* __restrict__ yh_g, const bf16* __restrict__ yl_g,   // [B*S][208]
    const bf16* __restrict__ sh_g, const bf16* __restrict__ sl_g,   // [B*S][128]
    bf16* __restrict__ ath, bf16* __restrict__ atl)                  // [B*S][128]
{
    extern __shared__ uint32_t smw[];
    const uint32_t base_b = smem_u32(smw);
    const int tid  = threadIdx.x;
    const int wid  = tid >> 5;
    const int lane = tid & 31;
    const int g    = lane >> 2;
    const int c    = lane & 3;
    const int bb   = blockIdx.y;
    const int q0   = blockIdx.x * 128;
    const int q0w  = wid * 16;
    const size_t bbS = (size_t)bb * SEQ;

    // ldmatrix per-thread offsets (words)
    const int qrow_off = (q0w + (lane & 15)) * 108 + (lane >> 4) * 4;
    const int yrow_off = (8 * (lane >> 4) + (lane & 7)) * 108 + ((lane >> 3) & 1) * 4;
    const int srow_off = (((lane >> 3) & 1) * 8 + (lane & 7)) * 68 + (lane >> 4) * 4;
    const uint32_t qh_b = base_b + AT_QH * 4 + qrow_off * 4;
    const uint32_t ql_b = base_b + AT_QL * 4 + qrow_off * 4;
    const uint32_t yh_b = base_b + AT_YH * 4 + yrow_off * 4;
    const uint32_t yl_b = base_b + AT_YL * 4 + yrow_off * 4;
    const uint32_t sh_b = base_b + AT_SH * 4 + srow_off * 4;
    const uint32_t sl_b = base_b + AT_SL * 4 + srow_off * 4;

    // ---- Q tile: 128 rows x 26 chunks x {hi,lo} = 6656 copies ----
#pragma unroll
    for (int j = 0; j < 26; j++) {
        int idx = tid + 256 * j;
        int half = idx >= 3328;
        int i2 = half ? idx - 3328 : idx;
        int row = i2 / 26, ch = i2 - row * 26;
        const bf16* src = (half ? ql_g : qh_g) + (bbS + q0 + row) * QP + ch * 8;
        uint32_t dst = base_b + ((half ? AT_QL : AT_QH) + row * 108 + ch * 4) * 4;
        cpa16(dst, src);
    }

    float m0v = -1e30f, m1v = -1e30f, l0v = 0.f, l1v = 0.f;
    float acc[16][4];
#pragma unroll
    for (int t = 0; t < 16; t++)
#pragma unroll
        for (int r = 0; r < 4; r++) acc[t][r] = 0.f;

    for (int s0 = 0; s0 < SEQ; s0 += 64) {
        __syncthreads();   // previous tile's reads complete

        // Y tile: 64 rows x 26 chunks x {hi,lo} = 3328 copies
#pragma unroll
        for (int j = 0; j < 13; j++) {
            int idx = tid + 256 * j;
            int half = idx >= 1664;
            int i2 = half ? idx - 1664 : idx;
            int row = i2 / 26, ch = i2 - row * 26;
            const bf16* src = (half ? yl_g : yh_g) + (bbS + s0 + row) * QP + ch * 8;
            uint32_t dst = base_b + ((half ? AT_YL : AT_YH) + row * 108 + ch * 4) * 4;
            cpa16(dst, src);
        }
        // SRL tile: 64 rows x 16 chunks x {hi,lo} = 2048 copies
#pragma unroll
        for (int j = 0; j < 8; j++) {
            int idx = tid + 256 * j;
            int half = idx >= 1024;
            int i2 = half ? idx - 1024 : idx;
            int row = i2 >> 4, ch = i2 & 15;
            const bf16* src = (half ? sl_g : sh_g) + (bbS + s0 + row) * VDIM + ch * 8;
            uint32_t dst = base_b + ((half ? AT_SL : AT_SH) + row * 68 + ch * 4) * 4;
            cpa16(dst, src);
        }
        CP_COMMIT();
        CP_WAIT(0);
        __syncthreads();

        // ---- QK^T ----
        float sc[8][4];
#pragma unroll
        for (int t = 0; t < 8; t++)
#pragma unroll
            for (int r = 0; r < 4; r++) sc[t][r] = 0.f;

#pragma unroll
        for (int h = 0; h < 13; h++) {
            uint32_t ah[4], al[4];
            ldmx4(ah, qh_b + h * 32);
            ldmx4(al, ql_b + h * 32);
#pragma unroll
            for (int t2 = 0; t2 < 4; t2++) {
                uint32_t bh[4], bl[4];
                ldmx4(bh, yh_b + (t2 * 1728 + h * 8) * 4);
                ldmx4(bl, yl_b + (t2 * 1728 + h * 8) * 4);
                mma2(sc[2 * t2],     ah, bh[0], bh[1]);
                mma2(sc[2 * t2],     al, bh[0], bh[1]);
                mma2(sc[2 * t2],     ah, bl[0], bl[1]);
                mma2(sc[2 * t2 + 1], ah, bh[2], bh[3]);
                mma2(sc[2 * t2 + 1], al, bh[2], bh[3]);
                mma2(sc[2 * t2 + 1], ah, bl[2], bl[3]);
            }
        }

        // ---- online softmax ----
        float mx0 = sc[0][0], mx1 = sc[0][2];
#pragma unroll
        for (int t = 0; t < 8; t++) {
            mx0 = fmaxf(mx0, fmaxf(sc[t][0], sc[t][1]));
            mx1 = fmaxf(mx1, fmaxf(sc[t][2], sc[t][3]));
        }
        mx0 = fmaxf(mx0, __shfl_xor_sync(0xffffffffu, mx0, 1));
        mx0 = fmaxf(mx0, __shfl_xor_sync(0xffffffffu, mx0, 2));
        mx1 = fmaxf(mx1, __shfl_xor_sync(0xffffffffu, mx1, 1));
        mx1 = fmaxf(mx1, __shfl_xor_sync(0xffffffffu, mx1, 2));
        float mn0 = fmaxf(m0v, mx0), mn1 = fmaxf(m1v, mx1);
        float ts0 = 0.f, ts1 = 0.f;
#pragma unroll
        for (int t = 0; t < 8; t++) {
            sc[t][0] = __expf(sc[t][0] - mn0); ts0 += sc[t][0];
            sc[t][1] = __expf(sc[t][1] - mn0); ts0 += sc[t][1];
            sc[t][2] = __expf(sc[t][2] - mn1); ts1 += sc[t][2];
            sc[t][3] = __expf(sc[t][3] - mn1); ts1 += sc[t][3];
        }
        ts0 += __shfl_xor_sync(0xffffffffu, ts0, 1);
        ts0 += __shfl_xor_sync(0xffffffffu, ts0, 2);
        ts1 += __shfl_xor_sync(0xffffffffu, ts1, 1);
        ts1 += __shfl_xor_sync(0xffffffffu, ts1, 2);
        float f0 = __expf(m0v - mn0), f1 = __expf(m1v - mn1);
        l0v = l0v * f0 + ts0; l1v = l1v * f1 + ts1;
        m0v = mn0; m1v = mn1;
#pragma unroll
        for (int t = 0; t < 16; t++) {
            acc[t][0] *= f0; acc[t][1] *= f0;
            acc[t][2] *= f1; acc[t][3] *= f1;
        }

        // ---- PV (P split in regs) ----
#pragma unroll
        for (int h = 0; h < 4; h++) {
            uint32_t pah[4], pal[4];
            split_pack2(sc[2 * h][0],     sc[2 * h][1],     pah[0], pal[0]);
            split_pack2(sc[2 * h][2],     sc[2 * h][3],     pah[1], pal[1]);
            split_pack2(sc[2 * h + 1][0], sc[2 * h + 1][1], pah[2], pal[2]);
            split_pack2(sc[2 * h + 1][2], sc[2 * h + 1][3], pah[3], pal[3]);
#pragma unroll
            for (int t2 = 0; t2 < 8; t2++) {
                uint32_t bh[4], bl[4];
                ldmx4t(bh, sh_b + (h * 1088 + t2 * 8) * 4);
                ldmx4t(bl, sl_b + (h * 1088 + t2 * 8) * 4);
                mma2(acc[2 * t2],     pah, bh[0], bh[1]);
                mma2(acc[2 * t2],     pal, bh[0], bh[1]);
                mma2(acc[2 * t2],     pah, bl[0], bl[1]);
                mma2(acc[2 * t2 + 1], pah, bh[2], bh[3]);
                mma2(acc[2 * t2 + 1], pal, bh[2], bh[3]);
                mma2(acc[2 * t2 + 1], pah, bl[2], bl[3]);
            }
        }
    }

    // ---- normalize + split-store att ----
    float inv0 = 1.f / l0v, inv1 = 1.f / l1v;
    int row0 = q0 + q0w + g;
    size_t b0 = (bbS + row0) * VDIM;
    size_t b1 = b0 + 8 * VDIM;
    uint32_t* ah32 = (uint32_t*)ath;
    uint32_t* al32 = (uint32_t*)atl;
#pragma unroll
    for (int t = 0; t < 16; t++) {
        int col = 8 * t + 2 * c;
        uint32_t h0, l0, h1, l1;
        split_pack2(acc[t][0] * inv0, acc[t][1] * inv0, h0, l0);
        split_pack2(acc[t][2] * inv1, acc[t][3] * inv1, h1, l1);
        ah32[(b0 + col) >> 1] = h0; al32[(b0 + col) >> 1] = l0;
        ah32[(b1 + col) >> 1] = h1; al32[(b1 + col) >> 1] = l1;
    }
}

// =====================================================================
// launcher
// =====================================================================
extern "C" void kernel_launch(void* const* d_in, const int* in_sizes, int n_in,
                              void* d_out, int out_size)
{
    (void)in_sizes; (void)n_in; (void)out_size;
    const float* mem = (const float*)d_in[0];   // [32,1024,200]
    const float* srl = (const float*)d_in[1];   // [32,1024,128]
    const float* emb = (const float*)d_in[2];   // [32,1024,768]
    const float* W1  = (const float*)d_in[4];   // [768,300]
    const float* b1  = (const float*)d_in[5];
    const float* W2  = (const float*)d_in[6];   // [300,200]
    const float* b2  = (const float*)d_in[7];
    const float* mat = (const float*)d_in[8];   // [200,200]
    const float* Wp  = (const float*)d_in[9];   // [128,128]
    const float* bp  = (const float*)d_in[10];
    float* outp = (float*)d_out;                // [32768,128]

#define SYM(v, s) cudaGetSymbolAddress((void**)&v, s)
    bf16 *embh, *embl, *memh, *meml, *srlh, *srll;
    bf16 *hh, *hl, *qh, *ql, *yh, *yl, *ath, *atl;
    bf16 *w1th, *w1tl, *w2th, *w2tl, *math_, *matl, *wph, *wpl;
    float *b1p, *b2p;
    SYM(embh, g_embh); SYM(embl, g_embl);
    SYM(memh, g_memh); SYM(meml, g_meml);
    SYM(srlh, g_srlh); SYM(srll, g_srll);
    SYM(hh, g_hh); SYM(hl, g_hl);
    SYM(qh, g_qh); SYM(ql, g_ql);
    SYM(yh, g_yh); SYM(yl, g_yl);
    SYM(ath, g_ath); SYM(atl, g_atl);
    SYM(w1th, g_w1th); SYM(w1tl, g_w1tl);
    SYM(w2th, g_w2th); SYM(w2tl, g_w2tl);
    SYM(math_, g_math); SYM(matl, g_matl);
    SYM(wph, g_wph); SYM(wpl, g_wpl);
    SYM(b1p, g_b1p); SYM(b2p, g_b2p);
#undef SYM

    cudaFuncSetAttribute(attn_kernel,
                         cudaFuncAttributeMaxDynamicSharedMemorySize, ATTN_SMEM_BYTES);
    cudaFuncSetAttribute(gemm_bf16<true, true>,
                         cudaFuncAttributeMaxDynamicSharedMemorySize, GEMM_SMEM_BYTES);
    cudaFuncSetAttribute(gemm_bf16<false, true>,
                         cudaFuncAttributeMaxDynamicSharedMemorySize, GEMM_SMEM_BYTES);
    cudaFuncSetAttribute(gemm_bf16<false, false>,
                         cudaFuncAttributeMaxDynamicSharedMemorySize, GEMM_SMEM_BYTES);

    // ---- prep: split inputs / transpose+split weights / pad biases ----
    {
        long long n2;
        n2 = (long long)MTOT * EMB / 2;
        split_pad2<<<(unsigned)((n2 + 255) / 256), 256>>>(emb, embh, embl, n2, EMB, EMB);
        n2 = (long long)MTOT * MEMP / 2;
        split_pad2<<<(unsigned)((n2 + 255) / 256), 256>>>(mem, memh, meml, n2, DDIM, MEMP);
        n2 = (long long)MTOT * VDIM / 2;
        split_pad2<<<(unsigned)((n2 + 255) / 256), 256>>>(srl, srlh, srll, n2, VDIM, VDIM);
        n2 = (long long)VDIM * VDIM / 2;
        split_pad2<<<(unsigned)((n2 + 255) / 256), 256>>>(Wp, wph, wpl, n2, VDIM, VDIM);
        tsplit<<<(W1NP * EMB + 255) / 256, 256>>>(W1, w1th, w1tl, EMB, H1, EMB, W1NP);
        tsplit<<<(W2NP * HP + 255) / 256, 256>>>(W2, w2th, w2tl, H1, DDIM, HP, W2NP);
        tsplit<<<(MATNP * MEMP + 255) / 256, 256>>>(mat, math_, matl, DDIM, DDIM, MEMP, MATNP);
        padbias<<<(HP + 255) / 256, 256>>>(b1, b1p, H1, HP);
        padbias<<<(QP + 255) / 256, 256>>>(b2, b2p, DDIM, QP);
    }

    // G1: h = relu(emb @ W1 + b1) -> split bf16 [32768][320]
    gemm_bf16<true, true><<<dim3(3, 256), 256, GEMM_SMEM_BYTES>>>(
        embh, embl, w1th, w1tl, b1p, nullptr, hh, hl, HP, EMB);
    // G2: q = relu(h @ W2 + b2) -> split bf16 [32768][208]
    gemm_bf16<true, true><<<dim3(2, 256), 256, GEMM_SMEM_BYTES>>>(
        hh, hl, w2th, w2tl, b2p, nullptr, qh, ql, QP, HP);
    // G3: y = mem @ matrix -> split bf16 [32768][208]
    gemm_bf16<false, true><<<dim3(2, 256), 256, GEMM_SMEM_BYTES>>>(
        memh, meml, math_, matl, nullptr, nullptr, yh, yl, QP, MEMP);
    // attention -> att split bf16 [32768][128]
    attn_kernel<<<dim3(SEQ / 128, BATCH), 256, ATTN_SMEM_BYTES>>>(
        qh, ql, yh, yl, srlh, srll, ath, atl);
    // G5: out = att @ Wp^T + bp -> fp32
    gemm_bf16<false, false><<<dim3(1, 256), 256, GEMM_SMEM_BYTES>>>(
        ath, atl, wph, wpl, bp, outp, nullptr, nullptr, VDIM, VDIM);
}

// round 10
// speedup vs baseline: 2.2217x; 1.0087x over previous
#include <cuda_runtime.h>
#include <cuda_bf16.h>
#include <cstdint>
#include <cstddef>

// Problem constants
#define BATCH 32
#define SEQ   1024
#define VDIM  128
#define EMB   768
#define H1    300
#define DDIM  200
#define MTOT  (BATCH*SEQ)   // 32768

// padded dims
#define HP    320
#define QP    208
#define MEMP  224
#define W1NP  384
#define W2NP  256
#define MATNP 256

typedef __nv_bfloat16 bf16;

// ---------------- helpers ----------------
__device__ __forceinline__ uint32_t pack_bf16(bf16 lo16, bf16 hi16) {
    __nv_bfloat162 t(lo16, hi16);
    return *(uint32_t*)&t;
}
__device__ __forceinline__ void split_bf16(float v, bf16& h, bf16& l) {
    h = __float2bfloat16(v);
    l = __float2bfloat16(v - __bfloat162float(h));
}
__device__ __forceinline__ void split_pack2(float x, float y, uint32_t& hi, uint32_t& lo) {
    bf16 hx, lx, hy, ly;
    split_bf16(x, hx, lx);
    split_bf16(y, hy, ly);
    hi = pack_bf16(hx, hy);
    lo = pack_bf16(lx, ly);
}
__device__ __forceinline__ void mma16816(float* d, const uint32_t* a, const uint32_t* b) {
    asm volatile(
        "mma.sync.aligned.m16n8k16.row.col.f32.bf16.bf16.f32 "
        "{%0,%1,%2,%3}, {%4,%5,%6,%7}, {%8,%9}, {%0,%1,%2,%3};"
        : "+f"(d[0]), "+f"(d[1]), "+f"(d[2]), "+f"(d[3])
        : "r"(a[0]), "r"(a[1]), "r"(a[2]), "r"(a[3]), "r"(b[0]), "r"(b[1]));
}
__device__ __forceinline__ void mma2(float* d, const uint32_t* a, uint32_t b0, uint32_t b1) {
    asm volatile(
        "mma.sync.aligned.m16n8k16.row.col.f32.bf16.bf16.f32 "
        "{%0,%1,%2,%3}, {%4,%5,%6,%7}, {%8,%9}, {%0,%1,%2,%3};"
        : "+f"(d[0]), "+f"(d[1]), "+f"(d[2]), "+f"(d[3])
        : "r"(a[0]), "r"(a[1]), "r"(a[2]), "r"(a[3]), "r"(b0), "r"(b1));
}
__device__ __forceinline__ uint32_t smem_u32(const void* p) {
    uint32_t a;
    asm("{ .reg .u64 t; cvta.to.shared.u64 t, %1; cvt.u32.u64 %0, t; }"
        : "=r"(a) : "l"(p));
    return a;
}
__device__ __forceinline__ void ldmx4(uint32_t* r, uint32_t addr) {
    asm volatile("ldmatrix.sync.aligned.m8n8.x4.shared.b16 {%0,%1,%2,%3}, [%4];"
        : "=r"(r[0]), "=r"(r[1]), "=r"(r[2]), "=r"(r[3]) : "r"(addr));
}
__device__ __forceinline__ void ldmx4t(uint32_t* r, uint32_t addr) {
    asm volatile("ldmatrix.sync.aligned.m8n8.x4.trans.shared.b16 {%0,%1,%2,%3}, [%4];"
        : "=r"(r[0]), "=r"(r[1]), "=r"(r[2]), "=r"(r[3]) : "r"(addr));
}
__device__ __forceinline__ void cpa16(uint32_t dst, const void* src) {
    asm volatile("cp.async.cg.shared.global [%0], [%1], 16;" :: "r"(dst), "l"(src));
}
#define CP_COMMIT() asm volatile("cp.async.commit_group;" ::: "memory")
#define CP_WAIT(n)  asm volatile("cp.async.wait_group %0;" :: "n"(n) : "memory")

// ---------------- static scratch (bf16 hi/lo pairs) ----------------
__device__ __align__(128) bf16 g_embh[(size_t)MTOT * EMB],  g_embl[(size_t)MTOT * EMB];
__device__ __align__(128) bf16 g_memh[(size_t)MTOT * MEMP], g_meml[(size_t)MTOT * MEMP];
__device__ __align__(128) bf16 g_srlh[(size_t)MTOT * VDIM], g_srll[(size_t)MTOT * VDIM];
__device__ __align__(128) bf16 g_hh[(size_t)MTOT * HP],     g_hl[(size_t)MTOT * HP];
__device__ __align__(128) bf16 g_qh[(size_t)MTOT * QP],     g_ql[(size_t)MTOT * QP];
__device__ __align__(128) bf16 g_yh[(size_t)MTOT * QP],     g_yl[(size_t)MTOT * QP];
__device__ __align__(128) bf16 g_ath[(size_t)MTOT * VDIM],  g_atl[(size_t)MTOT * VDIM];
__device__ __align__(128) bf16 g_w1th[W1NP * EMB],  g_w1tl[W1NP * EMB];
__device__ __align__(128) bf16 g_w2th[W2NP * HP],   g_w2tl[W2NP * HP];
__device__ __align__(128) bf16 g_math[MATNP * MEMP], g_matl[MATNP * MEMP];
__device__ __align__(128) bf16 g_wph[VDIM * VDIM],  g_wpl[VDIM * VDIM];
__device__ __align__(128) float g_b1p[HP];
__device__ __align__(128) float g_b2p[QP];

// ---------------- prep kernels ----------------
__global__ void split_pad2(const float* __restrict__ in, bf16* __restrict__ oh,
                           bf16* __restrict__ ol, long long n2, int C, int CP)
{
    long long i2 = (long long)blockIdx.x * blockDim.x + threadIdx.x;
    if (i2 >= n2) return;
    int cp2 = CP >> 1;
    long long r = i2 / cp2;
    int c2 = (int)(i2 - r * cp2) * 2;
    float x = 0.f, y = 0.f;
    if (c2 + 1 < C) {
        float2 v = *(const float2*)(in + r * C + c2);
        x = v.x; y = v.y;
    } else if (c2 < C) {
        x = in[r * C + c2];
    }
    uint32_t h, l;
    split_pack2(x, y, h, l);
    ((uint32_t*)oh)[(r * CP + c2) >> 1] = h;
    ((uint32_t*)ol)[(r * CP + c2) >> 1] = l;
}

__global__ void tsplit(const float* __restrict__ in, bf16* __restrict__ oh,
                       bf16* __restrict__ ol, int K, int N, int KP, int NP)
{
    int i = blockIdx.x * blockDim.x + threadIdx.x;
    if (i >= NP * KP) return;
    int n = i / KP, k = i - n * KP;
    float v = (n < N && k < K) ? in[(size_t)k * N + n] : 0.f;
    bf16 h, l;
    split_bf16(v, h, l);
    oh[i] = h; ol[i] = l;
}

__global__ void padbias(const float* __restrict__ b, float* __restrict__ bp, int N, int NP)
{
    int i = blockIdx.x * blockDim.x + threadIdx.x;
    if (i < NP) bp[i] = (i < N) ? b[i] : 0.f;
}

// =====================================================================
// bf16 pre-split GEMM (unchanged from round 9, passing)
// =====================================================================
#define GSTRIDE_W 20
#define GSTAGE_W  (4 * 128 * GSTRIDE_W)
#define GEMM_SMEM_BYTES (2 * GSTAGE_W * 4)    // 81920

template<bool RELU, bool SPLITOUT>
__global__ __launch_bounds__(256) void gemm_bf16(
    const bf16* __restrict__ Ah, const bf16* __restrict__ Al,
    const bf16* __restrict__ Bh, const bf16* __restrict__ Bl,
    const float* __restrict__ bias,
    float* __restrict__ C, bf16* __restrict__ Ch, bf16* __restrict__ Cl,
    int Ns, int K)
{
    extern __shared__ uint32_t smw[];
    const uint32_t base_b = smem_u32(smw);

    const int tid  = threadIdx.x;
    const int wid  = tid >> 5;
    const int lane = tid & 31;
    const int g    = lane >> 2;
    const int c    = lane & 3;
    const int wm   = wid & 1;
    const int wn   = wid >> 1;
    const int m0 = blockIdx.y * 128;
    const int n0 = blockIdx.x * 128;

    float acc[4][4][4];
#pragma unroll
    for (int mi = 0; mi < 4; mi++)
#pragma unroll
        for (int ni = 0; ni < 4; ni++)
#pragma unroll
            for (int r = 0; r < 4; r++) acc[mi][ni][r] = 0.f;

    auto loadChunk = [&](int ck, int st) {
        const int k0 = ck << 5;
        const uint32_t stb = base_b + (st ? GSTAGE_W * 4 : 0);
#pragma unroll
        for (int j = 0; j < 8; j++) {
            int idx = tid + 256 * j;
            int which = idx >> 9;
            int row = (idx >> 2) & 127;
            int part = idx & 3;
            const bf16* base = (which == 0) ? Ah : (which == 1) ? Al
                             : (which == 2) ? Bh : Bl;
            size_t grow = (which < 2) ? (size_t)(m0 + row) * K
                                      : (size_t)(n0 + row) * K;
            uint32_t dst = stb + (which * 2560 + row * GSTRIDE_W + part * 4) * 4;
            cpa16(dst, base + grow + k0 + part * 8);
        }
    };

    auto compute = [&](int st) {
        uint32_t* sAh = smw + st * GSTAGE_W;
        uint32_t* sAl = sAh + 2560;
        uint32_t* sBh = sAh + 5120;
        uint32_t* sBl = sAh + 7680;
#pragma unroll
        for (int ks = 0; ks < 2; ks++) {
            const int kw = ks * 8;
            uint32_t bh[4][2], bl[4][2];
#pragma unroll
            for (int ni = 0; ni < 4; ni++) {
                int base = (wn * 32 + ni * 8 + g) * GSTRIDE_W + kw + c;
                bh[ni][0] = sBh[base]; bh[ni][1] = sBh[base + 4];
                bl[ni][0] = sBl[base]; bl[ni][1] = sBl[base + 4];
            }
#pragma unroll
            for (int mi = 0; mi < 4; mi++) {
                int base = (wm * 64 + mi * 16 + g) * GSTRIDE_W + kw + c;
                uint32_t ah[4], al[4];
                ah[0] = sAh[base];       ah[1] = sAh[base + 8 * GSTRIDE_W];
                ah[2] = sAh[base + 4];   ah[3] = sAh[base + 4 + 8 * GSTRIDE_W];
                al[0] = sAl[base];       al[1] = sAl[base + 8 * GSTRIDE_W];
                al[2] = sAl[base + 4];   al[3] = sAl[base + 4 + 8 * GSTRIDE_W];
#pragma unroll
                for (int ni = 0; ni < 4; ni++) {
                    mma16816(acc[mi][ni], ah, bh[ni]);
                    mma16816(acc[mi][ni], al, bh[ni]);
                    mma16816(acc[mi][ni], ah, bl[ni]);
                }
            }
        }
    };

    const int nch = K >> 5;

    loadChunk(0, 0);
    CP_COMMIT();
    if (nch > 1) loadChunk(1, 1);
    CP_COMMIT();

    for (int ck = 0; ck < nch; ck++) {
        CP_WAIT(1);
        __syncthreads();
        compute(ck & 1);
        __syncthreads();
        if (ck + 2 < nch) loadChunk(ck + 2, ck & 1);
        CP_COMMIT();
    }

#pragma unroll
    for (int mi = 0; mi < 4; mi++) {
#pragma unroll
        for (int ni = 0; ni < 4; ni++) {
            int row = m0 + wm * 64 + mi * 16 + g;
            int col = n0 + wn * 32 + ni * 8 + 2 * c;
            if (col < Ns) {
                float bx = 0.f, by = 0.f;
                if (bias != nullptr) { bx = bias[col]; by = bias[col + 1]; }
                float2 o0, o1;
                o0.x = acc[mi][ni][0] + bx; o0.y = acc[mi][ni][1] + by;
                o1.x = acc[mi][ni][2] + bx; o1.y = acc[mi][ni][3] + by;
                if (RELU) {
                    o0.x = fmaxf(o0.x, 0.f); o0.y = fmaxf(o0.y, 0.f);
                    o1.x = fmaxf(o1.x, 0.f); o1.y = fmaxf(o1.y, 0.f);
                }
                if (SPLITOUT) {
                    uint32_t h0, l0, h1, l1;
                    split_pack2(o0.x, o0.y, h0, l0);
                    split_pack2(o1.x, o1.y, h1, l1);
                    size_t w0 = ((size_t)row * Ns + col) >> 1;
                    size_t w1 = ((size_t)(row + 8) * Ns + col) >> 1;
                    ((uint32_t*)Ch)[w0] = h0; ((uint32_t*)Cl)[w0] = l0;
                    ((uint32_t*)Ch)[w1] = h1; ((uint32_t*)Cl)[w1] = l1;
                } else {
                    *(float2*)(C + (size_t)row * Ns + col) = o0;
                    *(float2*)(C + (size_t)(row + 8) * Ns + col) = o1;
                }
            }
        }
    }
}

// =====================================================================
// Flash attention v3: Q fragments live in REGISTERS (loaded once via
// ldmatrix from a staging area); Y/SRL double-buffered via cp.async.
// 128 q x 64 s tiles, 8 warps x 16 q-rows, K = 208 (13 k16 steps).
//
// smem: 2 stages x [ yh 64x108 | yl 64x108 | sh 64x68 | sl 64x68 ]
//       = 2 x 22528 words = 45056 words = 180224 B.
// Q staging (prologue only) reuses the same region: qh @0, ql @13824.
// =====================================================================
#define AT_STG_W   22528
#define AT_YL_OFF  6912
#define AT_SH_OFF  13824
#define AT_SL_OFF  18176
#define ATTN_SMEM_BYTES (2 * AT_STG_W * 4)   // 180224

__global__ __launch_bounds__(256) void attn_kernel(
    const bf16* __restrict__ qh_g, const bf16* __restrict__ ql_g,   // [B*S][208]
    const bf16* __restrict__ yh_g, const bf16* __restrict__ yl_g,   // [B*S][208]
    const bf16* __restrict__ sh_g, const bf16* __restrict__ sl_g,   // [B*S][128]
    bf16* __restrict__ ath, bf16* __restrict__ atl)                  // [B*S][128]
{
    extern __shared__ uint32_t smw[];
    const uint32_t base_b = smem_u32(smw);
    const int tid  = threadIdx.x;
    const int wid  = tid >> 5;
    const int lane = tid & 31;
    const int g    = lane >> 2;
    const int c    = lane & 3;
    const int bb   = blockIdx.y;
    const int q0   = blockIdx.x * 128;
    const int q0w  = wid * 16;
    const size_t bbS = (size_t)bb * SEQ;

    // per-thread ldmatrix offsets (words)
    const int qrow_off = (q0w + (lane & 15)) * 108 + (lane >> 4) * 4;
    const int yrow_off = (8 * (lane >> 4) + (lane & 7)) * 108 + ((lane >> 3) & 1) * 4;
    const int srow_off = (((lane >> 3) & 1) * 8 + (lane & 7)) * 68 + (lane >> 4) * 4;

    // ---- stage Q into smem (transient), then ldmatrix -> registers ----
#pragma unroll
    for (int j = 0; j < 26; j++) {
        int idx = tid + 256 * j;
        int half = idx >= 3328;
        int i2 = half ? idx - 3328 : idx;
        int row = i2 / 26, ch = i2 - row * 26;
        const bf16* src = (half ? ql_g : qh_g) + (bbS + q0 + row) * QP + ch * 8;
        uint32_t dst = base_b + ((half ? AT_SH_OFF : 0) + row * 108 + ch * 4) * 4;
        cpa16(dst, src);
    }
    CP_COMMIT();
    CP_WAIT(0);
    __syncthreads();

    uint32_t qrh[13][4], qrl[13][4];
    {
        const uint32_t qh_b = base_b + qrow_off * 4;
        const uint32_t ql_b = base_b + (AT_SH_OFF + qrow_off) * 4;
#pragma unroll
        for (int h = 0; h < 13; h++) {
            ldmx4(qrh[h], qh_b + h * 32);
            ldmx4(qrl[h], ql_b + h * 32);
        }
    }
    __syncthreads();   // all warps done reading staged Q before pipeline overwrites

    float m0v = -1e30f, m1v = -1e30f, l0v = 0.f, l1v = 0.f;
    float acc[16][4];
#pragma unroll
    for (int t = 0; t < 16; t++)
#pragma unroll
        for (int r = 0; r < 4; r++) acc[t][r] = 0.f;

    auto loadTile = [&](int s0, int stg) {
        const uint32_t sb = base_b + stg * (AT_STG_W * 4);
        // Y tile: 64 rows x 26 chunks x {hi,lo}
#pragma unroll
        for (int j = 0; j < 13; j++) {
            int idx = tid + 256 * j;
            int half = idx >= 1664;
            int i2 = half ? idx - 1664 : idx;
            int row = i2 / 26, ch = i2 - row * 26;
            const bf16* src = (half ? yl_g : yh_g) + (bbS + s0 + row) * QP + ch * 8;
            cpa16(sb + ((half ? AT_YL_OFF : 0) + row * 108 + ch * 4) * 4, src);
        }
        // SRL tile: 64 rows x 16 chunks x {hi,lo}
#pragma unroll
        for (int j = 0; j < 8; j++) {
            int idx = tid + 256 * j;
            int half = idx >= 1024;
            int i2 = half ? idx - 1024 : idx;
            int row = i2 >> 4, ch = i2 & 15;
            const bf16* src = (half ? sl_g : sh_g) + (bbS + s0 + row) * VDIM + ch * 8;
            cpa16(sb + ((half ? AT_SL_OFF : AT_SH_OFF) + row * 68 + ch * 4) * 4, src);
        }
    };

    // pipeline prologue: tile 0 -> stage 0
    loadTile(0, 0);
    CP_COMMIT();

    for (int t = 0; t < 16; t++) {
        __syncthreads();   // previous compute done before overwriting its stage
        if (t + 1 < 16) loadTile((t + 1) * 64, (t + 1) & 1);
        CP_COMMIT();
        CP_WAIT(1);        // tile t complete; tile t+1 still in flight
        __syncthreads();

        const int stg = t & 1;
        const uint32_t yh_b = base_b + (stg * AT_STG_W + yrow_off) * 4;
        const uint32_t yl_b = yh_b + AT_YL_OFF * 4;
        const uint32_t sh_b = base_b + (stg * AT_STG_W + AT_SH_OFF + srow_off) * 4;
        const uint32_t sl_b = base_b + (stg * AT_STG_W + AT_SL_OFF + srow_off) * 4;

        // ---- QK^T (Q from registers) ----
        float sc[8][4];
#pragma unroll
        for (int t8 = 0; t8 < 8; t8++)
#pragma unroll
            for (int r = 0; r < 4; r++) sc[t8][r] = 0.f;

#pragma unroll
        for (int h = 0; h < 13; h++) {
#pragma unroll
            for (int t2 = 0; t2 < 4; t2++) {
                uint32_t bh[4], bl[4];
                ldmx4(bh, yh_b + (t2 * 1728 + h * 8) * 4);
                ldmx4(bl, yl_b + (t2 * 1728 + h * 8) * 4);
                mma2(sc[2 * t2],     qrh[h], bh[0], bh[1]);
                mma2(sc[2 * t2],     qrl[h], bh[0], bh[1]);
                mma2(sc[2 * t2],     qrh[h], bl[0], bl[1]);
                mma2(sc[2 * t2 + 1], qrh[h], bh[2], bh[3]);
                mma2(sc[2 * t2 + 1], qrl[h], bh[2], bh[3]);
                mma2(sc[2 * t2 + 1], qrh[h], bl[2], bl[3]);
            }
        }

        // ---- online softmax ----
        float mx0 = sc[0][0], mx1 = sc[0][2];
#pragma unroll
        for (int t8 = 0; t8 < 8; t8++) {
            mx0 = fmaxf(mx0, fmaxf(sc[t8][0], sc[t8][1]));
            mx1 = fmaxf(mx1, fmaxf(sc[t8][2], sc[t8][3]));
        }
        mx0 = fmaxf(mx0, __shfl_xor_sync(0xffffffffu, mx0, 1));
        mx0 = fmaxf(mx0, __shfl_xor_sync(0xffffffffu, mx0, 2));
        mx1 = fmaxf(mx1, __shfl_xor_sync(0xffffffffu, mx1, 1));
        mx1 = fmaxf(mx1, __shfl_xor_sync(0xffffffffu, mx1, 2));
        float mn0 = fmaxf(m0v, mx0), mn1 = fmaxf(m1v, mx1);
        float ts0 = 0.f, ts1 = 0.f;
#pragma unroll
        for (int t8 = 0; t8 < 8; t8++) {
            sc[t8][0] = __expf(sc[t8][0] - mn0); ts0 += sc[t8][0];
            sc[t8][1] = __expf(sc[t8][1] - mn0); ts0 += sc[t8][1];
            sc[t8][2] = __expf(sc[t8][2] - mn1); ts1 += sc[t8][2];
            sc[t8][3] = __expf(sc[t8][3] - mn1); ts1 += sc[t8][3];
        }
        ts0 += __shfl_xor_sync(0xffffffffu, ts0, 1);
        ts0 += __shfl_xor_sync(0xffffffffu, ts0, 2);
        ts1 += __shfl_xor_sync(0xffffffffu, ts1, 1);
        ts1 += __shfl_xor_sync(0xffffffffu, ts1, 2);
        float f0 = __expf(m0v - mn0), f1 = __expf(m1v - mn1);
        l0v = l0v * f0 + ts0; l1v = l1v * f1 + ts1;
        m0v = mn0; m1v = mn1;
#pragma unroll
        for (int t16 = 0; t16 < 16; t16++) {
            acc[t16][0] *= f0; acc[t16][1] *= f0;
            acc[t16][2] *= f1; acc[t16][3] *= f1;
        }

        // ---- PV (P split in regs) ----
#pragma unroll
        for (int h = 0; h < 4; h++) {
            uint32_t pah[4], pal[4];
            split_pack2(sc[2 * h][0],     sc[2 * h][1],     pah[0], pal[0]);
            split_pack2(sc[2 * h][2],     sc[2 * h][3],     pah[1], pal[1]);
            split_pack2(sc[2 * h + 1][0], sc[2 * h + 1][1], pah[2], pal[2]);
            split_pack2(sc[2 * h + 1][2], sc[2 * h + 1][3], pah[3], pal[3]);
#pragma unroll
            for (int t2 = 0; t2 < 8; t2++) {
                uint32_t bh[4], bl[4];
                ldmx4t(bh, sh_b + (h * 1088 + t2 * 8) * 4);
                ldmx4t(bl, sl_b + (h * 1088 + t2 * 8) * 4);
                mma2(acc[2 * t2],     pah, bh[0], bh[1]);
                mma2(acc[2 * t2],     pal, bh[0], bh[1]);
                mma2(acc[2 * t2],     pah, bl[0], bl[1]);
                mma2(acc[2 * t2 + 1], pah, bh[2], bh[3]);
                mma2(acc[2 * t2 + 1], pal, bh[2], bh[3]);
                mma2(acc[2 * t2 + 1], pah, bl[2], bl[3]);
            }
        }
    }

    // ---- normalize + split-store att ----
    float inv0 = 1.f / l0v, inv1 = 1.f / l1v;
    int row0 = q0 + q0w + g;
    size_t b0 = (bbS + row0) * VDIM;
    size_t b1 = b0 + 8 * VDIM;
    uint32_t* ah32 = (uint32_t*)ath;
    uint32_t* al32 = (uint32_t*)atl;
#pragma unroll
    for (int t = 0; t < 16; t++) {
        int col = 8 * t + 2 * c;
        uint32_t h0, l0, h1, l1;
        split_pack2(acc[t][0] * inv0, acc[t][1] * inv0, h0, l0);
        split_pack2(acc[t][2] * inv1, acc[t][3] * inv1, h1, l1);
        ah32[(b0 + col) >> 1] = h0; al32[(b0 + col) >> 1] = l0;
        ah32[(b1 + col) >> 1] = h1; al32[(b1 + col) >> 1] = l1;
    }
}

// =====================================================================
// launcher
// =====================================================================
extern "C" void kernel_launch(void* const* d_in, const int* in_sizes, int n_in,
                              void* d_out, int out_size)
{
    (void)in_sizes; (void)n_in; (void)out_size;
    const float* mem = (const float*)d_in[0];
    const float* srl = (const float*)d_in[1];
    const float* emb = (const float*)d_in[2];
    const float* W1  = (const float*)d_in[4];
    const float* b1  = (const float*)d_in[5];
    const float* W2  = (const float*)d_in[6];
    const float* b2  = (const float*)d_in[7];
    const float* mat = (const float*)d_in[8];
    const float* Wp  = (const float*)d_in[9];
    const float* bp  = (const float*)d_in[10];
    float* outp = (float*)d_out;

#define SYM(v, s) cudaGetSymbolAddress((void**)&v, s)
    bf16 *embh, *embl, *memh, *meml, *srlh, *srll;
    bf16 *hh, *hl, *qh, *ql, *yh, *yl, *ath, *atl;
    bf16 *w1th, *w1tl, *w2th, *w2tl, *math_, *matl, *wph, *wpl;
    float *b1p, *b2p;
    SYM(embh, g_embh); SYM(embl, g_embl);
    SYM(memh, g_memh); SYM(meml, g_meml);
    SYM(srlh, g_srlh); SYM(srll, g_srll);
    SYM(hh, g_hh); SYM(hl, g_hl);
    SYM(qh, g_qh); SYM(ql, g_ql);
    SYM(yh, g_yh); SYM(yl, g_yl);
    SYM(ath, g_ath); SYM(atl, g_atl);
    SYM(w1th, g_w1th); SYM(w1tl, g_w1tl);
    SYM(w2th, g_w2th); SYM(w2tl, g_w2tl);
    SYM(math_, g_math); SYM(matl, g_matl);
    SYM(wph, g_wph); SYM(wpl, g_wpl);
    SYM(b1p, g_b1p); SYM(b2p, g_b2p);
#undef SYM

    cudaFuncSetAttribute(attn_kernel,
                         cudaFuncAttributeMaxDynamicSharedMemorySize, ATTN_SMEM_BYTES);
    cudaFuncSetAttribute(gemm_bf16<true, true>,
                         cudaFuncAttributeMaxDynamicSharedMemorySize, GEMM_SMEM_BYTES);
    cudaFuncSetAttribute(gemm_bf16<false, true>,
                         cudaFuncAttributeMaxDynamicSharedMemorySize, GEMM_SMEM_BYTES);
    cudaFuncSetAttribute(gemm_bf16<false, false>,
                         cudaFuncAttributeMaxDynamicSharedMemorySize, GEMM_SMEM_BYTES);

    // ---- prep ----
    {
        long long n2;
        n2 = (long long)MTOT * EMB / 2;
        split_pad2<<<(unsigned)((n2 + 255) / 256), 256>>>(emb, embh, embl, n2, EMB, EMB);
        n2 = (long long)MTOT * MEMP / 2;
        split_pad2<<<(unsigned)((n2 + 255) / 256), 256>>>(mem, memh, meml, n2, DDIM, MEMP);
        n2 = (long long)MTOT * VDIM / 2;
        split_pad2<<<(unsigned)((n2 + 255) / 256), 256>>>(srl, srlh, srll, n2, VDIM, VDIM);
        n2 = (long long)VDIM * VDIM / 2;
        split_pad2<<<(unsigned)((n2 + 255) / 256), 256>>>(Wp, wph, wpl, n2, VDIM, VDIM);
        tsplit<<<(W1NP * EMB + 255) / 256, 256>>>(W1, w1th, w1tl, EMB, H1, EMB, W1NP);
        tsplit<<<(W2NP * HP + 255) / 256, 256>>>(W2, w2th, w2tl, H1, DDIM, HP, W2NP);
        tsplit<<<(MATNP * MEMP + 255) / 256, 256>>>(mat, math_, matl, DDIM, DDIM, MEMP, MATNP);
        padbias<<<(HP + 255) / 256, 256>>>(b1, b1p, H1, HP);
        padbias<<<(QP + 255) / 256, 256>>>(b2, b2p, DDIM, QP);
    }

    // G1: h = relu(emb @ W1 + b1) -> split bf16 [32768][320]
    gemm_bf16<true, true><<<dim3(3, 256), 256, GEMM_SMEM_BYTES>>>(
        embh, embl, w1th, w1tl, b1p, nullptr, hh, hl, HP, EMB);
    // G2: q = relu(h @ W2 + b2) -> split bf16 [32768][208]
    gemm_bf16<true, true><<<dim3(2, 256), 256, GEMM_SMEM_BYTES>>>(
        hh, hl, w2th, w2tl, b2p, nullptr, qh, ql, QP, HP);
    // G3: y = mem @ matrix -> split bf16 [32768][208]
    gemm_bf16<false, true><<<dim3(2, 256), 256, GEMM_SMEM_BYTES>>>(
        memh, meml, math_, matl, nullptr, nullptr, yh, yl, QP, MEMP);
    // attention -> att split bf16 [32768][128]
    attn_kernel<<<dim3(SEQ / 128, BATCH), 256, ATTN_SMEM_BYTES>>>(
        qh, ql, yh, yl, srlh, srll, ath, atl);
    // G5: out = att @ Wp^T + bp -> fp32
    gemm_bf16<false, false><<<dim3(1, 256), 256, GEMM_SMEM_BYTES>>>(
        ath, atl, wph, wpl, bp, outp, nullptr, nullptr, VDIM, VDIM);
}